// round 10
// baseline (speedup 1.0000x reference)
#include <cuda_runtime.h>
#include <cuda_fp16.h>
#include <math.h>
#include <stdint.h>

// Problem dims (fixed)
#define BATCH 4
#define SEQ   4096
#define DIM   1024
#define HEADS 16
#define DFF   4096
#define ROWS  16384
#define QKVW  3072

// ---------------------------------------------------------------------------
// Scratch (device globals; no runtime allocation allowed)
// ---------------------------------------------------------------------------
__device__ __half g_h1  [ROWS*(size_t)DIM];
__device__ __half g_qkv [ROWS*(size_t)QKVW];
__device__ __half g_ao  [ROWS*(size_t)DIM];
__device__ float  g_x2  [ROWS*(size_t)DIM];
__device__ __half g_h2  [ROWS*(size_t)DIM];
__device__ float  g_dot [BATCH*HEADS*(size_t)SEQ];
__device__ __half g_act [ROWS*(size_t)DFF];
__device__ __half g_wqkvT[(size_t)QKVW*DIM];   // [3072][1024] K-major (N rows)
__device__ __half g_woT [(size_t)DIM*DIM];
__device__ __half g_w1T [(size_t)DFF*DIM];
__device__ __half g_w2T [(size_t)DIM*DFF];

// ---------------------------------------------------------------------------
// Helpers
// ---------------------------------------------------------------------------
__device__ __forceinline__ float gelu_exact(float x) {
    return 0.5f * x * (1.0f + erff(x * 0.70710678118654752f));
}
__device__ __forceinline__ uint32_t smem_u32(const void* p) {
    uint32_t a;
    asm("{ .reg .u64 t; cvta.to.shared.u64 t, %1; cvt.u32.u64 %0, t; }"
        : "=r"(a) : "l"(p));
    return a;
}
__device__ __forceinline__ void cp16(uint32_t dst, const void* src) {
    asm volatile("cp.async.cg.shared.global [%0], [%1], 16;" :: "r"(dst), "l"(src));
}
__device__ __forceinline__ void cp_commit() {
    asm volatile("cp.async.commit_group;" ::: "memory");
}
#define LDMX4(r0, r1, r2, r3, addr)                                           \
    asm volatile("ldmatrix.sync.aligned.m8n8.x4.shared.b16 {%0,%1,%2,%3}, [%4];" \
        : "=r"(r0), "=r"(r1), "=r"(r2), "=r"(r3) : "r"(addr))

// smem row: 32 k-halves data + 8 pad halves -> stride 40 halves (80B).
// Rows r within an 8-row ldmatrix tile hit banks (r*20)%32: all distinct.
#define OP_B     10240                     // bytes per operand tile (128*80)
#define STAGE_B  (2*OP_B)                  // 20480
#define STAGES   4
#define SMEM_DYN (STAGES*STAGE_B)          // 81920

// ---------------------------------------------------------------------------
// FP16 tensor-core GEMM: C[M,N] = A[M,K] @ Bt[N,K]^T  (A,Bt fp16)
//  EPI 0: store half           (C = __half*)
//  EPI 1: float store +res+bias (C = float*, res fp32)
//  EPI 2: half store gelu(+bias)
// CTA 128x128, 128 threads (4 warps 2x2, warp tile 64x64), k-chunk 32,
// 4-stage cp.async pipeline, ldmatrix fragment loads.  (R5/R9-proven config,
// UNCHANGED.)
// ---------------------------------------------------------------------------
template <int EPI>
__global__ __launch_bounds__(128, 2) void gemm_fp16(
    const __half* __restrict__ A, const __half* __restrict__ Bt,
    void* __restrict__ Cv, const float* __restrict__ res,
    const float* __restrict__ bias, int M, int N, int K)
{
    extern __shared__ char smc[];
    const uint32_t smb = smem_u32(smc);

    const int tid  = threadIdx.x;
    const int lane = tid & 31;
    const int wid  = tid >> 5;
    const int wm   = wid >> 1;
    const int wn   = wid & 1;
    const int g    = lane >> 2;
    const int t    = lane & 3;
    const int m0   = blockIdx.y << 7;
    const int n0   = blockIdx.x << 7;

    // ldmatrix per-lane base offsets (bytes within stage)
    const uint32_t aoff =
        (uint32_t)(((wm * 64 + (lane & 7) + 8 * ((lane >> 3) & 1)) * 40 +
                    8 * (lane >> 4)) * 2);
    const uint32_t boff =
        (uint32_t)(OP_B + (((wn * 64 + (lane & 7) + 8 * (lane >> 4)) * 40 +
                            8 * ((lane >> 3) & 1)) * 2));

    // staging: per operand 512 granules of 16B; 4 per thread
    uint32_t sA[4], sB[4];
    const __half* gA[4];
    const __half* gB[4];
#pragma unroll
    for (int j = 0; j < 4; j++) {
        const int gid = j * 128 + tid;
        const int row = gid >> 2, c = gid & 3;
        sA[j] = (uint32_t)(row * 80 + c * 16);
        sB[j] = (uint32_t)(OP_B + row * 80 + c * 16);
        gA[j] = A  + (size_t)(m0 + row) * K + c * 8;
        gB[j] = Bt + (size_t)(n0 + row) * K + c * 8;
    }

    float acc[4][8][4];
#pragma unroll
    for (int i = 0; i < 4; i++)
#pragma unroll
        for (int j = 0; j < 8; j++)
#pragma unroll
            for (int r = 0; r < 4; r++) acc[i][j][r] = 0.f;

    const int KT = K >> 5;

#pragma unroll
    for (int s = 0; s < STAGES; s++) {
        const uint32_t base = smb + s * STAGE_B;
        const int ko = s * 32;
#pragma unroll
        for (int j = 0; j < 4; j++) {
            cp16(base + sA[j], gA[j] + ko);
            cp16(base + sB[j], gB[j] + ko);
        }
        cp_commit();
    }

    for (int kt = 0; kt < KT; kt++) {
        asm volatile("cp.async.wait_group %0;" :: "n"(STAGES - 1) : "memory");
        __syncthreads();

        const uint32_t stg = smb + (kt % STAGES) * STAGE_B;

#pragma unroll
        for (int kc = 0; kc < 2; kc++) {
            const uint32_t kb = kc * 32;            // 16 halves
            uint32_t af[4][4];
#pragma unroll
            for (int i = 0; i < 4; i++)
                LDMX4(af[i][0], af[i][1], af[i][2], af[i][3],
                      stg + aoff + i * 1280 + kb);
            uint32_t bf[8][2];
#pragma unroll
            for (int jj = 0; jj < 4; jj++)
                LDMX4(bf[2 * jj][0], bf[2 * jj][1],
                      bf[2 * jj + 1][0], bf[2 * jj + 1][1],
                      stg + boff + jj * 1280 + kb);
#pragma unroll
            for (int i = 0; i < 4; i++)
#pragma unroll
                for (int j = 0; j < 8; j++) {
                    asm volatile(
                        "mma.sync.aligned.m16n8k16.row.col.f32.f16.f16.f32 "
                        "{%0,%1,%2,%3}, {%4,%5,%6,%7}, {%8,%9}, {%0,%1,%2,%3};"
                        : "+f"(acc[i][j][0]), "+f"(acc[i][j][1]),
                          "+f"(acc[i][j][2]), "+f"(acc[i][j][3])
                        : "r"(af[i][0]), "r"(af[i][1]),
                          "r"(af[i][2]), "r"(af[i][3]),
                          "r"(bf[j][0]), "r"(bf[j][1]));
                }
        }
        __syncthreads();

        const int nk = kt + STAGES;
        if (nk < KT) {
            const uint32_t base = smb + (nk % STAGES) * STAGE_B;
            const int ko = nk * 32;
#pragma unroll
            for (int j = 0; j < 4; j++) {
                cp16(base + sA[j], gA[j] + ko);
                cp16(base + sB[j], gB[j] + ko);
            }
        }
        cp_commit();
    }

    // epilogue
#pragma unroll
    for (int j = 0; j < 8; j++) {
        const int col = n0 + wn * 64 + j * 8 + t * 2;
        float2 bv = make_float2(0.f, 0.f);
        if (EPI != 0) bv = *(const float2*)&bias[col];
#pragma unroll
        for (int i = 0; i < 4; i++) {
            const int row0 = m0 + wm * 64 + i * 16 + g;
#pragma unroll
            for (int h = 0; h < 2; h++) {
                const int r = row0 + 8 * h;
                const float a = acc[i][j][2 * h + 0];
                const float b = acc[i][j][2 * h + 1];
                if (EPI == 0) {
                    *(__half2*)((__half*)Cv + (size_t)r * N + col) =
                        __floats2half2_rn(a, b);
                } else if (EPI == 1) {
                    const float2 rv = *(const float2*)&res[(size_t)r * N + col];
                    float2 o;
                    o.x = a + rv.x + bv.x;
                    o.y = b + rv.y + bv.y;
                    *(float2*)((float*)Cv + (size_t)r * N + col) = o;
                } else {
                    *(__half2*)((__half*)Cv + (size_t)r * N + col) =
                        __floats2half2_rn(gelu_exact(a + bv.x),
                                          gelu_exact(b + bv.y));
                }
            }
        }
    }
}

// ---------------------------------------------------------------------------
// Prep kernel: 6 weight transposes AND LN1 in ONE launch (they are
// independent; merging overlaps them and removes a serialized launch).
//   blocks [0,4096)      : 4 square transpose jobs wq/wk/wv/wo (1024x1024)
//   blocks [4096,8192)   : w1 [1024][4096] -> w1T
//   blocks [8192,12288)  : w2 [4096][1024] -> w2T
//   blocks [12288,28672) : LN1 row = blk-12288  (x -> h1 fp16)
// ---------------------------------------------------------------------------
__global__ __launch_bounds__(256) void prep_kernel(
    const float* __restrict__ wq, const float* __restrict__ wk,
    const float* __restrict__ wv, const float* __restrict__ wo,
    const float* __restrict__ w1, const float* __restrict__ w2,
    __half* __restrict__ wqkvT, __half* __restrict__ woT,
    __half* __restrict__ w1T, __half* __restrict__ w2T,
    const float* __restrict__ x, const float* __restrict__ gam,
    const float* __restrict__ bet, __half* __restrict__ h1out)
{
    const int blk = blockIdx.x;
    if (blk < 12288) {
        // ---- transpose tile ----
        __shared__ float sh[32][33];
        const float* in;
        __half* out;
        int R, C, cx, ry;
        if (blk < 4096) {
            const int job = blk >> 10, loc = blk & 1023;
            cx = loc & 31; ry = loc >> 5; R = 1024; C = 1024;
            if (job == 0)      { in = wq; out = wqkvT; }
            else if (job == 1) { in = wk; out = wqkvT + (size_t)1024 * 1024; }
            else if (job == 2) { in = wv; out = wqkvT + (size_t)2 * 1024 * 1024; }
            else               { in = wo; out = woT; }
        } else if (blk < 8192) {
            const int loc = blk - 4096;
            cx = loc & 127; ry = loc >> 7; R = 1024; C = 4096;
            in = w1; out = w1T;
        } else {
            const int loc = blk - 8192;
            cx = loc & 31; ry = loc >> 5; R = 4096; C = 1024;
            in = w2; out = w2T;
        }
        const int c0 = cx * 32, r0 = ry * 32;
        const int tx = threadIdx.x & 31, ty = threadIdx.x >> 5;
#pragma unroll
        for (int j = 0; j < 4; j++)
            sh[ty + j * 8][tx] = in[(size_t)(r0 + ty + j * 8) * C + c0 + tx];
        __syncthreads();
#pragma unroll
        for (int j = 0; j < 4; j++)
            out[(size_t)(c0 + ty + j * 8) * R + r0 + tx] =
                __float2half(sh[tx][ty + j * 8]);
    } else {
        // ---- LayerNorm row ----
        const int row = blk - 12288;
        const float* xr = x + (size_t)row * DIM;
        float v[4];
        float s = 0.f, ss = 0.f;
#pragma unroll
        for (int i = 0; i < 4; i++) {
            v[i] = xr[threadIdx.x + i * 256];
            s += v[i]; ss += v[i] * v[i];
        }
#pragma unroll
        for (int o = 16; o; o >>= 1) {
            s  += __shfl_xor_sync(0xffffffffu, s, o);
            ss += __shfl_xor_sync(0xffffffffu, ss, o);
        }
        __shared__ float sh1[8], sh2[8];
        const int w = threadIdx.x >> 5, l = threadIdx.x & 31;
        if (l == 0) { sh1[w] = s; sh2[w] = ss; }
        __syncthreads();
        s = 0.f; ss = 0.f;
#pragma unroll
        for (int i = 0; i < 8; i++) { s += sh1[i]; ss += sh2[i]; }
        const float mu   = s * (1.0f / DIM);
        const float var  = ss * (1.0f / DIM) - mu * mu;
        const float rstd = rsqrtf(var + 1e-5f);
        __half* outr = h1out + (size_t)row * DIM;
#pragma unroll
        for (int i = 0; i < 4; i++) {
            int c = threadIdx.x + i * 256;
            outr[c] = __float2half((v[i] - mu) * rstd * gam[c] + bet[c]);
        }
    }
}

// ---------------------------------------------------------------------------
// LayerNorm -> fp16 output (LN2)
// ---------------------------------------------------------------------------
__global__ __launch_bounds__(256) void ln_kernel(
    const float* __restrict__ x, const float* __restrict__ gam,
    const float* __restrict__ bet, __half* __restrict__ out)
{
    const int row = blockIdx.x;
    const float* xr = x + (size_t)row * DIM;
    float v[4];
    float s = 0.f, ss = 0.f;
#pragma unroll
    for (int i = 0; i < 4; i++) {
        v[i] = xr[threadIdx.x + i * 256];
        s += v[i]; ss += v[i] * v[i];
    }
#pragma unroll
    for (int o = 16; o; o >>= 1) {
        s  += __shfl_xor_sync(0xffffffffu, s, o);
        ss += __shfl_xor_sync(0xffffffffu, ss, o);
    }
    __shared__ float sh1[8], sh2[8];
    const int w = threadIdx.x >> 5, l = threadIdx.x & 31;
    if (l == 0) { sh1[w] = s; sh2[w] = ss; }
    __syncthreads();
    s = 0.f; ss = 0.f;
#pragma unroll
    for (int i = 0; i < 8; i++) { s += sh1[i]; ss += sh2[i]; }
    const float mu   = s * (1.0f / DIM);
    const float var  = ss * (1.0f / DIM) - mu * mu;
    const float rstd = rsqrtf(var + 1e-5f);
    __half* outr = out + (size_t)row * DIM;
#pragma unroll
    for (int i = 0; i < 4; i++) {
        int c = threadIdx.x + i * 256;
        outr[c] = __float2half((v[i] - mu) * rstd * gam[c] + bet[c]);
    }
}

// ---------------------------------------------------------------------------
// Per-position head dots: single uint4 (16B) load per operand per thread
// ---------------------------------------------------------------------------
__global__ __launch_bounds__(128) void dots_kernel(
    const __half* __restrict__ qkv, float* __restrict__ dots)
{
    const int row = blockIdx.x;
    const int b = row >> 12, r = row & 4095;
    const int t = threadIdx.x;
    const uint4 qu = *(const uint4*)(qkv + (size_t)row * QKVW + 8 * t);
    const uint4 ku = *(const uint4*)(qkv + (size_t)row * QKVW + DIM + 8 * t);
    const __half2* qh = (const __half2*)&qu;
    const __half2* kh = (const __half2*)&ku;
    float p = 0.f;
#pragma unroll
    for (int i = 0; i < 4; i++) {
        const float2 a = __half22float2(qh[i]);
        const float2 c = __half22float2(kh[i]);
        p += a.x * c.x + a.y * c.y;
    }
#pragma unroll
    for (int o = 4; o; o >>= 1) p += __shfl_xor_sync(0xffffffffu, p, o);
    if ((t & 7) == 0)
        dots[((size_t)(b * HEADS + (t >> 3))) * SEQ + r] = p * 0.125f;
}

__global__ __launch_bounds__(1024) void softmax_kernel(float* __restrict__ d)
{
    const int row = blockIdx.x;
    float4* p = (float4*)(d + (size_t)row * SEQ);
    float4 v = p[threadIdx.x];
    float m = fmaxf(fmaxf(v.x, v.y), fmaxf(v.z, v.w));
#pragma unroll
    for (int o = 16; o; o >>= 1) m = fmaxf(m, __shfl_xor_sync(0xffffffffu, m, o));
    __shared__ float sm[32];
    const int w = threadIdx.x >> 5, l = threadIdx.x & 31;
    if (l == 0) sm[w] = m;
    __syncthreads();
    m = sm[0];
#pragma unroll
    for (int i = 1; i < 32; i++) m = fmaxf(m, sm[i]);
    __syncthreads();
    float4 e;
    e.x = expf(v.x - m); e.y = expf(v.y - m);
    e.z = expf(v.z - m); e.w = expf(v.w - m);
    float s = e.x + e.y + e.z + e.w;
#pragma unroll
    for (int o = 16; o; o >>= 1) s += __shfl_xor_sync(0xffffffffu, s, o);
    if (l == 0) sm[w] = s;
    __syncthreads();
    s = 0.f;
#pragma unroll
    for (int i = 0; i < 32; i++) s += sm[i];
    const float inv = 1.0f / s;
    e.x *= inv; e.y *= inv; e.z *= inv; e.w *= inv;
    p[threadIdx.x] = e;
}

// attn_out[b,n',c] = att[b, c/64, p(n')] * V[b, p(n'), c]; p(n')=(n'%128)*32+n'/128
// 16B vector load + 16B vector store per thread.
__global__ __launch_bounds__(128) void gather_kernel(
    const __half* __restrict__ qkv, const float* __restrict__ att,
    __half* __restrict__ out)
{
    const int nb = blockIdx.x;
    const int b = nb >> 12, n = nb & 4095;
    const int pidx = (n & 127) * 32 + (n >> 7);
    const int t = threadIdx.x;                 // covers channels 8t..8t+7
    const float a = att[((size_t)(b * HEADS + (t >> 3))) * SEQ + pidx];
    const uint4 vu = *(const uint4*)(qkv + ((size_t)((b << 12) + pidx)) * QKVW +
                                     2 * DIM + 8 * t);
    const __half2* vh = (const __half2*)&vu;
    uint4 ou;
    __half2* oh = (__half2*)&ou;
#pragma unroll
    for (int i = 0; i < 4; i++) {
        const float2 v = __half22float2(vh[i]);
        oh[i] = __floats2half2_rn(a * v.x, a * v.y);
    }
    *(uint4*)(out + (size_t)nb * DIM + 8 * t) = ou;
}

// ---------------------------------------------------------------------------
// Launch
// ---------------------------------------------------------------------------
extern "C" void kernel_launch(void* const* d_in, const int* in_sizes, int n_in,
                              void* d_out, int out_size)
{
    const float* x     = (const float*)d_in[0];
    const float* ln1_g = (const float*)d_in[1];
    const float* ln1_b = (const float*)d_in[2];
    const float* wq    = (const float*)d_in[3];
    const float* wk    = (const float*)d_in[4];
    const float* wv    = (const float*)d_in[5];
    const float* wo    = (const float*)d_in[6];
    const float* bo    = (const float*)d_in[7];
    const float* ln2_g = (const float*)d_in[8];
    const float* ln2_b = (const float*)d_in[9];
    const float* w1    = (const float*)d_in[10];
    const float* b1    = (const float*)d_in[11];
    const float* w2    = (const float*)d_in[12];
    const float* b2    = (const float*)d_in[13];
    float* out = (float*)d_out;

    __half *h1, *qkv, *ao, *h2, *act, *wqkvT, *woT, *w1T, *w2T;
    float *x2, *dots;
    cudaGetSymbolAddress((void**)&h1,   g_h1);
    cudaGetSymbolAddress((void**)&qkv,  g_qkv);
    cudaGetSymbolAddress((void**)&ao,   g_ao);
    cudaGetSymbolAddress((void**)&x2,   g_x2);
    cudaGetSymbolAddress((void**)&h2,   g_h2);
    cudaGetSymbolAddress((void**)&dots, g_dot);
    cudaGetSymbolAddress((void**)&act,  g_act);
    cudaGetSymbolAddress((void**)&wqkvT,g_wqkvT);
    cudaGetSymbolAddress((void**)&woT,  g_woT);
    cudaGetSymbolAddress((void**)&w1T,  g_w1T);
    cudaGetSymbolAddress((void**)&w2T,  g_w2T);

    cudaFuncSetAttribute(gemm_fp16<0>, cudaFuncAttributeMaxDynamicSharedMemorySize, SMEM_DYN);
    cudaFuncSetAttribute(gemm_fp16<1>, cudaFuncAttributeMaxDynamicSharedMemorySize, SMEM_DYN);
    cudaFuncSetAttribute(gemm_fp16<2>, cudaFuncAttributeMaxDynamicSharedMemorySize, SMEM_DYN);

    // 0. weight transposes + LN1 in ONE launch
    prep_kernel<<<28672, 256>>>(wq, wk, wv, wo, w1, w2,
                                wqkvT, woT, w1T, w2T,
                                x, ln1_g, ln1_b, h1);

    // 1. qkv = h1 @ [wq|wk|wv]  (fp16 out)
    gemm_fp16<0><<<dim3(QKVW/128, ROWS/128), 128, SMEM_DYN>>>(
        h1, wqkvT, qkv, nullptr, nullptr, ROWS, QKVW, DIM);
    // 2-4. diagonal dots -> softmax over sequence -> permuted gather * V
    dots_kernel<<<ROWS, 128>>>(qkv, dots);
    softmax_kernel<<<BATCH * HEADS, 1024>>>(dots);
    gather_kernel<<<ROWS, 128>>>(qkv, dots, ao);
    // 5. x2 = x + ao @ wo + bo  (fp32 out)
    gemm_fp16<1><<<dim3(DIM/128, ROWS/128), 128, SMEM_DYN>>>(
        ao, woT, x2, x, bo, ROWS, DIM, DIM);
    // 6. h2 = LN2(x2)  (fp16)
    ln_kernel<<<ROWS, 256>>>(x2, ln2_g, ln2_b, h2);
    // 7. act = gelu(h2 @ w1 + b1)  (fp16 out)
    gemm_fp16<2><<<dim3(DFF/128, ROWS/128), 128, SMEM_DYN>>>(
        h2, w1T, act, nullptr, b1, ROWS, DFF, DIM);
    // 8. out = x2 + act @ w2 + b2  (fp32 out)
    gemm_fp16<1><<<dim3(DIM/128, ROWS/128), 128, SMEM_DYN>>>(
        act, w2T, out, x2, b2, ROWS, DIM, DFF);
}

// round 11
// speedup vs baseline: 1.5333x; 1.5333x over previous
#include <cuda_runtime.h>
#include <cuda_fp16.h>
#include <math.h>
#include <stdint.h>

// Problem dims (fixed)
#define BATCH 4
#define SEQ   4096
#define DIM   1024
#define HEADS 16
#define DFF   4096
#define ROWS  16384
#define QKVW  3072

// ---------------------------------------------------------------------------
// Scratch (device globals; no runtime allocation allowed)
// ---------------------------------------------------------------------------
__device__ __half g_h1  [ROWS*(size_t)DIM];
__device__ __half g_qkv [ROWS*(size_t)QKVW];
__device__ __half g_ao  [ROWS*(size_t)DIM];
__device__ float  g_x2  [ROWS*(size_t)DIM];
__device__ __half g_h2  [ROWS*(size_t)DIM];
__device__ float  g_dot [BATCH*HEADS*(size_t)SEQ];
__device__ __half g_act [ROWS*(size_t)DFF];
__device__ __half g_wqkvT[(size_t)QKVW*DIM];   // [3072][1024] K-major (N rows)
__device__ __half g_woT [(size_t)DIM*DIM];
__device__ __half g_w1T [(size_t)DFF*DIM];
__device__ __half g_w2T [(size_t)DIM*DFF];

// ---------------------------------------------------------------------------
// Helpers
// ---------------------------------------------------------------------------
__device__ __forceinline__ float gelu_exact(float x) {
    return 0.5f * x * (1.0f + erff(x * 0.70710678118654752f));
}
__device__ __forceinline__ uint32_t smem_u32(const void* p) {
    uint32_t a;
    asm("{ .reg .u64 t; cvta.to.shared.u64 t, %1; cvt.u32.u64 %0, t; }"
        : "=r"(a) : "l"(p));
    return a;
}
__device__ __forceinline__ void cp16(uint32_t dst, const void* src) {
    asm volatile("cp.async.cg.shared.global [%0], [%1], 16;" :: "r"(dst), "l"(src));
}
__device__ __forceinline__ void cp_commit() {
    asm volatile("cp.async.commit_group;" ::: "memory");
}
#define LDMX4(r0, r1, r2, r3, addr)                                           \
    asm volatile("ldmatrix.sync.aligned.m8n8.x4.shared.b16 {%0,%1,%2,%3}, [%4];" \
        : "=r"(r0), "=r"(r1), "=r"(r2), "=r"(r3) : "r"(addr))

// smem row: 32 k-halves data + 8 pad halves -> stride 40 halves (80B).
// Rows r within an 8-row ldmatrix tile hit banks (r*20)%32: all distinct.
#define OP_B     10240                     // bytes per operand tile (128*80)
#define STAGE_B  (2*OP_B)                  // 20480
#define STAGES   4
#define SMEM_DYN (STAGES*STAGE_B)          // 81920

// ---------------------------------------------------------------------------
// FP16 tensor-core GEMM: C[M,N] = A[M,K] @ Bt[N,K]^T  (A,Bt fp16)
//  EPI 0: store half           (C = __half*)
//  EPI 1: float store +res+bias (C = float*, res fp32)
//  EPI 2: half store gelu(+bias)
// CTA 128x128, 128 threads (4 warps 2x2, warp tile 64x64), k-chunk 32,
// 4-stage cp.async pipeline, ldmatrix fragment loads.  (R5/R9-proven config.)
// ---------------------------------------------------------------------------
template <int EPI>
__global__ __launch_bounds__(128, 2) void gemm_fp16(
    const __half* __restrict__ A, const __half* __restrict__ Bt,
    void* __restrict__ Cv, const float* __restrict__ res,
    const float* __restrict__ bias, int M, int N, int K)
{
    extern __shared__ char smc[];
    const uint32_t smb = smem_u32(smc);

    const int tid  = threadIdx.x;
    const int lane = tid & 31;
    const int wid  = tid >> 5;
    const int wm   = wid >> 1;
    const int wn   = wid & 1;
    const int g    = lane >> 2;
    const int t    = lane & 3;
    const int m0   = blockIdx.y << 7;
    const int n0   = blockIdx.x << 7;

    // ldmatrix per-lane base offsets (bytes within stage)
    // A tiles: lanes 0-7:(r,k0) 8-15:(r+8,k0) 16-23:(r,k8) 24-31:(r+8,k8)
    const uint32_t aoff =
        (uint32_t)(((wm * 64 + (lane & 7) + 8 * ((lane >> 3) & 1)) * 40 +
                    8 * (lane >> 4)) * 2);
    // B tiles: lanes 0-7:(n,k0) 8-15:(n,k8) 16-23:(n+8,k0) 24-31:(n+8,k8)
    const uint32_t boff =
        (uint32_t)(OP_B + (((wn * 64 + (lane & 7) + 8 * (lane >> 4)) * 40 +
                            8 * ((lane >> 3) & 1)) * 2));

    // staging: per operand 512 granules of 16B; 4 per thread
    uint32_t sA[4], sB[4];
    const __half* gA[4];
    const __half* gB[4];
#pragma unroll
    for (int j = 0; j < 4; j++) {
        const int gid = j * 128 + tid;
        const int row = gid >> 2, c = gid & 3;
        sA[j] = (uint32_t)(row * 80 + c * 16);
        sB[j] = (uint32_t)(OP_B + row * 80 + c * 16);
        gA[j] = A  + (size_t)(m0 + row) * K + c * 8;
        gB[j] = Bt + (size_t)(n0 + row) * K + c * 8;
    }

    float acc[4][8][4];
#pragma unroll
    for (int i = 0; i < 4; i++)
#pragma unroll
        for (int j = 0; j < 8; j++)
#pragma unroll
            for (int r = 0; r < 4; r++) acc[i][j][r] = 0.f;

    const int KT = K >> 5;

#pragma unroll
    for (int s = 0; s < STAGES; s++) {
        const uint32_t base = smb + s * STAGE_B;
        const int ko = s * 32;
#pragma unroll
        for (int j = 0; j < 4; j++) {
            cp16(base + sA[j], gA[j] + ko);
            cp16(base + sB[j], gB[j] + ko);
        }
        cp_commit();
    }

    for (int kt = 0; kt < KT; kt++) {
        asm volatile("cp.async.wait_group %0;" :: "n"(STAGES - 1) : "memory");
        __syncthreads();

        const uint32_t stg = smb + (kt % STAGES) * STAGE_B;

#pragma unroll
        for (int kc = 0; kc < 2; kc++) {
            const uint32_t kb = kc * 32;            // 16 halves
            uint32_t af[4][4];
#pragma unroll
            for (int i = 0; i < 4; i++)
                LDMX4(af[i][0], af[i][1], af[i][2], af[i][3],
                      stg + aoff + i * 1280 + kb);
            uint32_t bf[8][2];
#pragma unroll
            for (int jj = 0; jj < 4; jj++)
                LDMX4(bf[2 * jj][0], bf[2 * jj][1],
                      bf[2 * jj + 1][0], bf[2 * jj + 1][1],
                      stg + boff + jj * 1280 + kb);
#pragma unroll
            for (int i = 0; i < 4; i++)
#pragma unroll
                for (int j = 0; j < 8; j++) {
                    asm volatile(
                        "mma.sync.aligned.m16n8k16.row.col.f32.f16.f16.f32 "
                        "{%0,%1,%2,%3}, {%4,%5,%6,%7}, {%8,%9}, {%0,%1,%2,%3};"
                        : "+f"(acc[i][j][0]), "+f"(acc[i][j][1]),
                          "+f"(acc[i][j][2]), "+f"(acc[i][j][3])
                        : "r"(af[i][0]), "r"(af[i][1]),
                          "r"(af[i][2]), "r"(af[i][3]),
                          "r"(bf[j][0]), "r"(bf[j][1]));
                }
        }
        __syncthreads();

        const int nk = kt + STAGES;
        if (nk < KT) {
            const uint32_t base = smb + (nk % STAGES) * STAGE_B;
            const int ko = nk * 32;
#pragma unroll
            for (int j = 0; j < 4; j++) {
                cp16(base + sA[j], gA[j] + ko);
                cp16(base + sB[j], gB[j] + ko);
            }
        }
        cp_commit();
    }

    // epilogue
#pragma unroll
    for (int j = 0; j < 8; j++) {
        const int col = n0 + wn * 64 + j * 8 + t * 2;
        float2 bv = make_float2(0.f, 0.f);
        if (EPI != 0) bv = *(const float2*)&bias[col];
#pragma unroll
        for (int i = 0; i < 4; i++) {
            const int row0 = m0 + wm * 64 + i * 16 + g;
#pragma unroll
            for (int h = 0; h < 2; h++) {
                const int r = row0 + 8 * h;
                const float a = acc[i][j][2 * h + 0];
                const float b = acc[i][j][2 * h + 1];
                if (EPI == 0) {
                    *(__half2*)((__half*)Cv + (size_t)r * N + col) =
                        __floats2half2_rn(a, b);
                } else if (EPI == 1) {
                    const float2 rv = *(const float2*)&res[(size_t)r * N + col];
                    float2 o;
                    o.x = a + rv.x + bv.x;
                    o.y = b + rv.y + bv.y;
                    *(float2*)((float*)Cv + (size_t)r * N + col) = o;
                } else {
                    *(__half2*)((__half*)Cv + (size_t)r * N + col) =
                        __floats2half2_rn(gelu_exact(a + bv.x),
                                          gelu_exact(b + bv.y));
                }
            }
        }
    }
}

// ---------------------------------------------------------------------------
// All 6 weight transposes in ONE launch. Tile t:
//   [0,4096)      4 square jobs wq/wk/wv/wo  (1024x1024, 32x32 grids)
//   [4096,8192)   w1 [1024][4096] -> w1T
//   [8192,12288)  w2 [4096][1024] -> w2T
// ---------------------------------------------------------------------------
__global__ __launch_bounds__(256) void transpose_all(
    const float* __restrict__ wq, const float* __restrict__ wk,
    const float* __restrict__ wv, const float* __restrict__ wo,
    const float* __restrict__ w1, const float* __restrict__ w2,
    __half* __restrict__ wqkvT, __half* __restrict__ woT,
    __half* __restrict__ w1T, __half* __restrict__ w2T)
{
    __shared__ float sh[32][33];
    const int tile = blockIdx.x;
    const float* in;
    __half* out;
    int R, C, cx, ry;
    if (tile < 4096) {
        const int job = tile >> 10, loc = tile & 1023;
        cx = loc & 31; ry = loc >> 5; R = 1024; C = 1024;
        if (job == 0)      { in = wq; out = wqkvT; }
        else if (job == 1) { in = wk; out = wqkvT + (size_t)1024 * 1024; }
        else if (job == 2) { in = wv; out = wqkvT + (size_t)2 * 1024 * 1024; }
        else               { in = wo; out = woT; }
    } else if (tile < 8192) {
        const int loc = tile - 4096;
        cx = loc & 127; ry = loc >> 7; R = 1024; C = 4096;
        in = w1; out = w1T;
    } else {
        const int loc = tile - 8192;
        cx = loc & 31; ry = loc >> 5; R = 4096; C = 1024;
        in = w2; out = w2T;
    }
    const int c0 = cx * 32, r0 = ry * 32;
    const int tx = threadIdx.x, ty = threadIdx.y;
#pragma unroll
    for (int j = 0; j < 4; j++)
        sh[ty + j * 8][tx] = in[(size_t)(r0 + ty + j * 8) * C + c0 + tx];
    __syncthreads();
#pragma unroll
    for (int j = 0; j < 4; j++)
        out[(size_t)(c0 + ty + j * 8) * R + r0 + tx] = __float2half(sh[tx][ty + j * 8]);
}

// ---------------------------------------------------------------------------
// LayerNorm -> fp16 output (feeds GEMM A)
// ---------------------------------------------------------------------------
__global__ __launch_bounds__(256) void ln_kernel(
    const float* __restrict__ x, const float* __restrict__ gam,
    const float* __restrict__ bet, __half* __restrict__ out)
{
    const int row = blockIdx.x;
    const float* xr = x + (size_t)row * DIM;
    float v[4];
    float s = 0.f, ss = 0.f;
#pragma unroll
    for (int i = 0; i < 4; i++) {
        v[i] = xr[threadIdx.x + i * 256];
        s += v[i]; ss += v[i] * v[i];
    }
#pragma unroll
    for (int o = 16; o; o >>= 1) {
        s  += __shfl_xor_sync(0xffffffffu, s, o);
        ss += __shfl_xor_sync(0xffffffffu, ss, o);
    }
    __shared__ float sh1[8], sh2[8];
    const int w = threadIdx.x >> 5, l = threadIdx.x & 31;
    if (l == 0) { sh1[w] = s; sh2[w] = ss; }
    __syncthreads();
    s = 0.f; ss = 0.f;
#pragma unroll
    for (int i = 0; i < 8; i++) { s += sh1[i]; ss += sh2[i]; }
    const float mu   = s * (1.0f / DIM);
    const float var  = ss * (1.0f / DIM) - mu * mu;
    const float rstd = rsqrtf(var + 1e-5f);
    __half* outr = out + (size_t)row * DIM;
#pragma unroll
    for (int i = 0; i < 4; i++) {
        int c = threadIdx.x + i * 256;
        outr[c] = __float2half((v[i] - mu) * rstd * gam[c] + bet[c]);
    }
}

// ---------------------------------------------------------------------------
// Per-position head dots from fp16 qkv: thread t covers 8 channels
// ---------------------------------------------------------------------------
__global__ __launch_bounds__(128) void dots_kernel(
    const __half* __restrict__ qkv, float* __restrict__ dots)
{
    const int row = blockIdx.x;
    const int b = row >> 12, r = row & 4095;
    const int t = threadIdx.x;
    const __half2* qr = (const __half2*)(qkv + (size_t)row * QKVW + 8 * t);
    const __half2* kr = (const __half2*)(qkv + (size_t)row * QKVW + DIM + 8 * t);
    float p = 0.f;
#pragma unroll
    for (int i = 0; i < 4; i++) {
        const float2 a = __half22float2(qr[i]);
        const float2 c = __half22float2(kr[i]);
        p += a.x * c.x + a.y * c.y;
    }
#pragma unroll
    for (int o = 4; o; o >>= 1) p += __shfl_xor_sync(0xffffffffu, p, o);
    if ((t & 7) == 0)
        dots[((size_t)(b * HEADS + (t >> 3))) * SEQ + r] = p * 0.125f;
}

__global__ __launch_bounds__(1024) void softmax_kernel(float* __restrict__ d)
{
    const int row = blockIdx.x;
    float4* p = (float4*)(d + (size_t)row * SEQ);
    float4 v = p[threadIdx.x];
    float m = fmaxf(fmaxf(v.x, v.y), fmaxf(v.z, v.w));
#pragma unroll
    for (int o = 16; o; o >>= 1) m = fmaxf(m, __shfl_xor_sync(0xffffffffu, m, o));
    __shared__ float sm[32];
    const int w = threadIdx.x >> 5, l = threadIdx.x & 31;
    if (l == 0) sm[w] = m;
    __syncthreads();
    m = sm[0];
#pragma unroll
    for (int i = 1; i < 32; i++) m = fmaxf(m, sm[i]);
    __syncthreads();
    float4 e;
    e.x = expf(v.x - m); e.y = expf(v.y - m);
    e.z = expf(v.z - m); e.w = expf(v.w - m);
    float s = e.x + e.y + e.z + e.w;
#pragma unroll
    for (int o = 16; o; o >>= 1) s += __shfl_xor_sync(0xffffffffu, s, o);
    if (l == 0) sm[w] = s;
    __syncthreads();
    s = 0.f;
#pragma unroll
    for (int i = 0; i < 32; i++) s += sm[i];
    const float inv = 1.0f / s;
    e.x *= inv; e.y *= inv; e.z *= inv; e.w *= inv;
    p[threadIdx.x] = e;
}

// attn_out[b,n',c] = att[b, c/64, p(n')] * V[b, p(n'), c]; p(n')=(n'%128)*32+n'/128
__global__ __launch_bounds__(128) void gather_kernel(
    const __half* __restrict__ qkv, const float* __restrict__ att,
    __half* __restrict__ out)
{
    const int nb = blockIdx.x;
    const int b = nb >> 12, n = nb & 4095;
    const int pidx = (n & 127) * 32 + (n >> 7);
    const int t = threadIdx.x;                 // covers channels 8t..8t+7
    const float a = att[((size_t)(b * HEADS + (t >> 3))) * SEQ + pidx];
    const __half2* vv =
        (const __half2*)(qkv + ((size_t)((b << 12) + pidx)) * QKVW + 2 * DIM + 8 * t);
    __half2* o = (__half2*)(out + (size_t)nb * DIM + 8 * t);
#pragma unroll
    for (int i = 0; i < 4; i++) {
        const float2 v = __half22float2(vv[i]);
        o[i] = __floats2half2_rn(a * v.x, a * v.y);
    }
}

// ---------------------------------------------------------------------------
// Launch
// ---------------------------------------------------------------------------
extern "C" void kernel_launch(void* const* d_in, const int* in_sizes, int n_in,
                              void* d_out, int out_size)
{
    const float* x     = (const float*)d_in[0];
    const float* ln1_g = (const float*)d_in[1];
    const float* ln1_b = (const float*)d_in[2];
    const float* wq    = (const float*)d_in[3];
    const float* wk    = (const float*)d_in[4];
    const float* wv    = (const float*)d_in[5];
    const float* wo    = (const float*)d_in[6];
    const float* bo    = (const float*)d_in[7];
    const float* ln2_g = (const float*)d_in[8];
    const float* ln2_b = (const float*)d_in[9];
    const float* w1    = (const float*)d_in[10];
    const float* b1    = (const float*)d_in[11];
    const float* w2    = (const float*)d_in[12];
    const float* b2    = (const float*)d_in[13];
    float* out = (float*)d_out;

    __half *h1, *qkv, *ao, *h2, *act, *wqkvT, *woT, *w1T, *w2T;
    float *x2, *dots;
    cudaGetSymbolAddress((void**)&h1,   g_h1);
    cudaGetSymbolAddress((void**)&qkv,  g_qkv);
    cudaGetSymbolAddress((void**)&ao,   g_ao);
    cudaGetSymbolAddress((void**)&x2,   g_x2);
    cudaGetSymbolAddress((void**)&h2,   g_h2);
    cudaGetSymbolAddress((void**)&dots, g_dot);
    cudaGetSymbolAddress((void**)&act,  g_act);
    cudaGetSymbolAddress((void**)&wqkvT,g_wqkvT);
    cudaGetSymbolAddress((void**)&woT,  g_woT);
    cudaGetSymbolAddress((void**)&w1T,  g_w1T);
    cudaGetSymbolAddress((void**)&w2T,  g_w2T);

    cudaFuncSetAttribute(gemm_fp16<0>, cudaFuncAttributeMaxDynamicSharedMemorySize, SMEM_DYN);
    cudaFuncSetAttribute(gemm_fp16<1>, cudaFuncAttributeMaxDynamicSharedMemorySize, SMEM_DYN);
    cudaFuncSetAttribute(gemm_fp16<2>, cudaFuncAttributeMaxDynamicSharedMemorySize, SMEM_DYN);

    // all 6 weight transposes in one launch (fp16 K-major B operands)
    transpose_all<<<12288, dim3(32, 8)>>>(wq, wk, wv, wo, w1, w2,
                                          wqkvT, woT, w1T, w2T);

    // 1. h1 = LN1(x)  (fp16)
    ln_kernel<<<ROWS, 256>>>(x, ln1_g, ln1_b, h1);
    // 2. qkv = h1 @ [wq|wk|wv]  (fp16 out)
    gemm_fp16<0><<<dim3(QKVW/128, ROWS/128), 128, SMEM_DYN>>>(
        h1, wqkvT, qkv, nullptr, nullptr, ROWS, QKVW, DIM);
    // 3-5. diagonal dots -> softmax over sequence -> permuted gather * V
    dots_kernel<<<ROWS, 128>>>(qkv, dots);
    softmax_kernel<<<BATCH * HEADS, 1024>>>(dots);
    gather_kernel<<<ROWS, 128>>>(qkv, dots, ao);
    // 6. x2 = x + ao @ wo + bo  (fp32 out)
    gemm_fp16<1><<<dim3(DIM/128, ROWS/128), 128, SMEM_DYN>>>(
        ao, woT, x2, x, bo, ROWS, DIM, DIM);
    // 7. h2 = LN2(x2)  (fp16)
    ln_kernel<<<ROWS, 256>>>(x2, ln2_g, ln2_b, h2);
    // 8. act = gelu(h2 @ w1 + b1)  (fp16 out)
    gemm_fp16<2><<<dim3(DFF/128, ROWS/128), 128, SMEM_DYN>>>(
        h2, w1T, act, nullptr, b1, ROWS, DFF, DIM);
    // 9. out = x2 + act @ w2 + b2  (fp32 out)
    gemm_fp16<1><<<dim3(DIM/128, ROWS/128), 128, SMEM_DYN>>>(
        act, w2T, out, x2, b2, ROWS, DIM, DFF);
}

// round 12
// speedup vs baseline: 1.5381x; 1.0031x over previous
#include <cuda_runtime.h>
#include <cuda_fp16.h>
#include <math.h>
#include <stdint.h>

// Problem dims (fixed)
#define BATCH 4
#define SEQ   4096
#define DIM   1024
#define HEADS 16
#define DFF   4096
#define ROWS  16384
#define QKVW  3072

// ---------------------------------------------------------------------------
// Scratch (device globals; no runtime allocation allowed)
// ---------------------------------------------------------------------------
__device__ __half g_h1  [ROWS*(size_t)DIM];
__device__ __half g_qkv [ROWS*(size_t)QKVW];
__device__ __half g_ao  [ROWS*(size_t)DIM];
__device__ float  g_x2  [ROWS*(size_t)DIM];
__device__ __half g_h2  [ROWS*(size_t)DIM];
__device__ float  g_dot [BATCH*HEADS*(size_t)SEQ];
__device__ __half g_act [ROWS*(size_t)DFF];
__device__ __half g_wqkvT[(size_t)QKVW*DIM];   // [3072][1024] K-major (N rows)
__device__ __half g_woT [(size_t)DIM*DIM];
__device__ __half g_w1T [(size_t)DFF*DIM];
__device__ __half g_w2T [(size_t)DIM*DFF];

// ---------------------------------------------------------------------------
// Helpers
// ---------------------------------------------------------------------------
__device__ __forceinline__ float gelu_exact(float x) {
    return 0.5f * x * (1.0f + erff(x * 0.70710678118654752f));
}
__device__ __forceinline__ uint32_t smem_u32(const void* p) {
    uint32_t a;
    asm("{ .reg .u64 t; cvta.to.shared.u64 t, %1; cvt.u32.u64 %0, t; }"
        : "=r"(a) : "l"(p));
    return a;
}
__device__ __forceinline__ void cp16(uint32_t dst, const void* src) {
    asm volatile("cp.async.cg.shared.global [%0], [%1], 16;" :: "r"(dst), "l"(src));
}
__device__ __forceinline__ void cp_commit() {
    asm volatile("cp.async.commit_group;" ::: "memory");
}
#define LDMX4(r0, r1, r2, r3, addr)                                           \
    asm volatile("ldmatrix.sync.aligned.m8n8.x4.shared.b16 {%0,%1,%2,%3}, [%4];" \
        : "=r"(r0), "=r"(r1), "=r"(r2), "=r"(r3) : "r"(addr))

// smem row: 32 k-halves data + 8 pad halves -> stride 40 halves (80B).
// Rows r within an 8-row ldmatrix tile hit banks (r*20)%32: all distinct.
#define OP_B     10240                     // bytes per operand tile (128*80)
#define STAGE_B  (2*OP_B)                  // 20480
#define STAGES   4
#define SMEM_DYN (STAGES*STAGE_B)          // 81920

// ---------------------------------------------------------------------------
// FP16 tensor-core GEMM: C[M,N] = A[M,K] @ Bt[N,K]^T  (A,Bt fp16)
//  EPI 0: store half           (C = __half*)
//  EPI 1: float store +res+bias (C = float*, res fp32)
//  EPI 2: half store gelu(+bias)
// CTA 128x128, 128 threads (4 warps 2x2, warp tile 64x64), k-chunk 32,
// 4-stage cp.async pipeline, ldmatrix fragment loads.  (R5/R9-proven config,
// UNCHANGED.)
// ---------------------------------------------------------------------------
template <int EPI>
__global__ __launch_bounds__(128, 2) void gemm_fp16(
    const __half* __restrict__ A, const __half* __restrict__ Bt,
    void* __restrict__ Cv, const float* __restrict__ res,
    const float* __restrict__ bias, int M, int N, int K)
{
    extern __shared__ char smc[];
    const uint32_t smb = smem_u32(smc);

    const int tid  = threadIdx.x;
    const int lane = tid & 31;
    const int wid  = tid >> 5;
    const int wm   = wid >> 1;
    const int wn   = wid & 1;
    const int g    = lane >> 2;
    const int t    = lane & 3;
    const int m0   = blockIdx.y << 7;
    const int n0   = blockIdx.x << 7;

    // ldmatrix per-lane base offsets (bytes within stage)
    // A tiles: lanes 0-7:(r,k0) 8-15:(r+8,k0) 16-23:(r,k8) 24-31:(r+8,k8)
    const uint32_t aoff =
        (uint32_t)(((wm * 64 + (lane & 7) + 8 * ((lane >> 3) & 1)) * 40 +
                    8 * (lane >> 4)) * 2);
    // B tiles: lanes 0-7:(n,k0) 8-15:(n,k8) 16-23:(n+8,k0) 24-31:(n+8,k8)
    const uint32_t boff =
        (uint32_t)(OP_B + (((wn * 64 + (lane & 7) + 8 * (lane >> 4)) * 40 +
                            8 * ((lane >> 3) & 1)) * 2));

    // staging: per operand 512 granules of 16B; 4 per thread
    uint32_t sA[4], sB[4];
    const __half* gA[4];
    const __half* gB[4];
#pragma unroll
    for (int j = 0; j < 4; j++) {
        const int gid = j * 128 + tid;
        const int row = gid >> 2, c = gid & 3;
        sA[j] = (uint32_t)(row * 80 + c * 16);
        sB[j] = (uint32_t)(OP_B + row * 80 + c * 16);
        gA[j] = A  + (size_t)(m0 + row) * K + c * 8;
        gB[j] = Bt + (size_t)(n0 + row) * K + c * 8;
    }

    float acc[4][8][4];
#pragma unroll
    for (int i = 0; i < 4; i++)
#pragma unroll
        for (int j = 0; j < 8; j++)
#pragma unroll
            for (int r = 0; r < 4; r++) acc[i][j][r] = 0.f;

    const int KT = K >> 5;

#pragma unroll
    for (int s = 0; s < STAGES; s++) {
        const uint32_t base = smb + s * STAGE_B;
        const int ko = s * 32;
#pragma unroll
        for (int j = 0; j < 4; j++) {
            cp16(base + sA[j], gA[j] + ko);
            cp16(base + sB[j], gB[j] + ko);
        }
        cp_commit();
    }

    for (int kt = 0; kt < KT; kt++) {
        asm volatile("cp.async.wait_group %0;" :: "n"(STAGES - 1) : "memory");
        __syncthreads();

        const uint32_t stg = smb + (kt % STAGES) * STAGE_B;

#pragma unroll
        for (int kc = 0; kc < 2; kc++) {
            const uint32_t kb = kc * 32;            // 16 halves
            uint32_t af[4][4];
#pragma unroll
            for (int i = 0; i < 4; i++)
                LDMX4(af[i][0], af[i][1], af[i][2], af[i][3],
                      stg + aoff + i * 1280 + kb);
            uint32_t bf[8][2];
#pragma unroll
            for (int jj = 0; jj < 4; jj++)
                LDMX4(bf[2 * jj][0], bf[2 * jj][1],
                      bf[2 * jj + 1][0], bf[2 * jj + 1][1],
                      stg + boff + jj * 1280 + kb);
#pragma unroll
            for (int i = 0; i < 4; i++)
#pragma unroll
                for (int j = 0; j < 8; j++) {
                    asm volatile(
                        "mma.sync.aligned.m16n8k16.row.col.f32.f16.f16.f32 "
                        "{%0,%1,%2,%3}, {%4,%5,%6,%7}, {%8,%9}, {%0,%1,%2,%3};"
                        : "+f"(acc[i][j][0]), "+f"(acc[i][j][1]),
                          "+f"(acc[i][j][2]), "+f"(acc[i][j][3])
                        : "r"(af[i][0]), "r"(af[i][1]),
                          "r"(af[i][2]), "r"(af[i][3]),
                          "r"(bf[j][0]), "r"(bf[j][1]));
                }
        }
        __syncthreads();

        const int nk = kt + STAGES;
        if (nk < KT) {
            const uint32_t base = smb + (nk % STAGES) * STAGE_B;
            const int ko = nk * 32;
#pragma unroll
            for (int j = 0; j < 4; j++) {
                cp16(base + sA[j], gA[j] + ko);
                cp16(base + sB[j], gB[j] + ko);
            }
        }
        cp_commit();
    }

    // epilogue
#pragma unroll
    for (int j = 0; j < 8; j++) {
        const int col = n0 + wn * 64 + j * 8 + t * 2;
        float2 bv = make_float2(0.f, 0.f);
        if (EPI != 0) bv = *(const float2*)&bias[col];
#pragma unroll
        for (int i = 0; i < 4; i++) {
            const int row0 = m0 + wm * 64 + i * 16 + g;
#pragma unroll
            for (int h = 0; h < 2; h++) {
                const int r = row0 + 8 * h;
                const float a = acc[i][j][2 * h + 0];
                const float b = acc[i][j][2 * h + 1];
                if (EPI == 0) {
                    *(__half2*)((__half*)Cv + (size_t)r * N + col) =
                        __floats2half2_rn(a, b);
                } else if (EPI == 1) {
                    const float2 rv = *(const float2*)&res[(size_t)r * N + col];
                    float2 o;
                    o.x = a + rv.x + bv.x;
                    o.y = b + rv.y + bv.y;
                    *(float2*)((float*)Cv + (size_t)r * N + col) = o;
                } else {
                    *(__half2*)((__half*)Cv + (size_t)r * N + col) =
                        __floats2half2_rn(gelu_exact(a + bv.x),
                                          gelu_exact(b + bv.y));
                }
            }
        }
    }
}

// ---------------------------------------------------------------------------
// All 6 weight transposes in ONE launch. Tile t:
//   [0,4096)      4 square jobs wq/wk/wv/wo  (1024x1024, 32x32 grids)
//   [4096,8192)   w1 [1024][4096] -> w1T
//   [8192,12288)  w2 [4096][1024] -> w2T
// ---------------------------------------------------------------------------
__global__ __launch_bounds__(256) void transpose_all(
    const float* __restrict__ wq, const float* __restrict__ wk,
    const float* __restrict__ wv, const float* __restrict__ wo,
    const float* __restrict__ w1, const float* __restrict__ w2,
    __half* __restrict__ wqkvT, __half* __restrict__ woT,
    __half* __restrict__ w1T, __half* __restrict__ w2T)
{
    __shared__ float sh[32][33];
    const int tile = blockIdx.x;
    const float* in;
    __half* out;
    int R, C, cx, ry;
    if (tile < 4096) {
        const int job = tile >> 10, loc = tile & 1023;
        cx = loc & 31; ry = loc >> 5; R = 1024; C = 1024;
        if (job == 0)      { in = wq; out = wqkvT; }
        else if (job == 1) { in = wk; out = wqkvT + (size_t)1024 * 1024; }
        else if (job == 2) { in = wv; out = wqkvT + (size_t)2 * 1024 * 1024; }
        else               { in = wo; out = woT; }
    } else if (tile < 8192) {
        const int loc = tile - 4096;
        cx = loc & 127; ry = loc >> 7; R = 1024; C = 4096;
        in = w1; out = w1T;
    } else {
        const int loc = tile - 8192;
        cx = loc & 31; ry = loc >> 5; R = 4096; C = 1024;
        in = w2; out = w2T;
    }
    const int c0 = cx * 32, r0 = ry * 32;
    const int tx = threadIdx.x, ty = threadIdx.y;
#pragma unroll
    for (int j = 0; j < 4; j++)
        sh[ty + j * 8][tx] = in[(size_t)(r0 + ty + j * 8) * C + c0 + tx];
    __syncthreads();
#pragma unroll
    for (int j = 0; j < 4; j++)
        out[(size_t)(c0 + ty + j * 8) * R + r0 + tx] = __float2half(sh[tx][ty + j * 8]);
}

// ---------------------------------------------------------------------------
// LayerNorm -> fp16 output (feeds GEMM A)
// ---------------------------------------------------------------------------
__global__ __launch_bounds__(256) void ln_kernel(
    const float* __restrict__ x, const float* __restrict__ gam,
    const float* __restrict__ bet, __half* __restrict__ out)
{
    const int row = blockIdx.x;
    const float* xr = x + (size_t)row * DIM;
    float v[4];
    float s = 0.f, ss = 0.f;
#pragma unroll
    for (int i = 0; i < 4; i++) {
        v[i] = xr[threadIdx.x + i * 256];
        s += v[i]; ss += v[i] * v[i];
    }
#pragma unroll
    for (int o = 16; o; o >>= 1) {
        s  += __shfl_xor_sync(0xffffffffu, s, o);
        ss += __shfl_xor_sync(0xffffffffu, ss, o);
    }
    __shared__ float sh1[8], sh2[8];
    const int w = threadIdx.x >> 5, l = threadIdx.x & 31;
    if (l == 0) { sh1[w] = s; sh2[w] = ss; }
    __syncthreads();
    s = 0.f; ss = 0.f;
#pragma unroll
    for (int i = 0; i < 8; i++) { s += sh1[i]; ss += sh2[i]; }
    const float mu   = s * (1.0f / DIM);
    const float var  = ss * (1.0f / DIM) - mu * mu;
    const float rstd = rsqrtf(var + 1e-5f);
    __half* outr = out + (size_t)row * DIM;
#pragma unroll
    for (int i = 0; i < 4; i++) {
        int c = threadIdx.x + i * 256;
        outr[c] = __float2half((v[i] - mu) * rstd * gam[c] + bet[c]);
    }
}

// ---------------------------------------------------------------------------
// Per-position head dots: ONE uint4 (16B) load per operand per thread
// (isolated R12 change #1)
// ---------------------------------------------------------------------------
__global__ __launch_bounds__(128) void dots_kernel(
    const __half* __restrict__ qkv, float* __restrict__ dots)
{
    const int row = blockIdx.x;
    const int b = row >> 12, r = row & 4095;
    const int t = threadIdx.x;
    const uint4 qu = *(const uint4*)(qkv + (size_t)row * QKVW + 8 * t);
    const uint4 ku = *(const uint4*)(qkv + (size_t)row * QKVW + DIM + 8 * t);
    const __half2* qh = (const __half2*)&qu;
    const __half2* kh = (const __half2*)&ku;
    float p = 0.f;
#pragma unroll
    for (int i = 0; i < 4; i++) {
        const float2 a = __half22float2(qh[i]);
        const float2 c = __half22float2(kh[i]);
        p += a.x * c.x + a.y * c.y;
    }
#pragma unroll
    for (int o = 4; o; o >>= 1) p += __shfl_xor_sync(0xffffffffu, p, o);
    if ((t & 7) == 0)
        dots[((size_t)(b * HEADS + (t >> 3))) * SEQ + r] = p * 0.125f;
}

__global__ __launch_bounds__(1024) void softmax_kernel(float* __restrict__ d)
{
    const int row = blockIdx.x;
    float4* p = (float4*)(d + (size_t)row * SEQ);
    float4 v = p[threadIdx.x];
    float m = fmaxf(fmaxf(v.x, v.y), fmaxf(v.z, v.w));
#pragma unroll
    for (int o = 16; o; o >>= 1) m = fmaxf(m, __shfl_xor_sync(0xffffffffu, m, o));
    __shared__ float sm[32];
    const int w = threadIdx.x >> 5, l = threadIdx.x & 31;
    if (l == 0) sm[w] = m;
    __syncthreads();
    m = sm[0];
#pragma unroll
    for (int i = 1; i < 32; i++) m = fmaxf(m, sm[i]);
    __syncthreads();
    float4 e;
    e.x = expf(v.x - m); e.y = expf(v.y - m);
    e.z = expf(v.z - m); e.w = expf(v.w - m);
    float s = e.x + e.y + e.z + e.w;
#pragma unroll
    for (int o = 16; o; o >>= 1) s += __shfl_xor_sync(0xffffffffu, s, o);
    if (l == 0) sm[w] = s;
    __syncthreads();
    s = 0.f;
#pragma unroll
    for (int i = 0; i < 32; i++) s += sm[i];
    const float inv = 1.0f / s;
    e.x *= inv; e.y *= inv; e.z *= inv; e.w *= inv;
    p[threadIdx.x] = e;
}

// attn_out[b,n',c] = att[b, c/64, p(n')] * V[b, p(n'), c]; p(n')=(n'%128)*32+n'/128
// 16B vector load + 16B vector store per thread (isolated R12 change #2)
__global__ __launch_bounds__(128) void gather_kernel(
    const __half* __restrict__ qkv, const float* __restrict__ att,
    __half* __restrict__ out)
{
    const int nb = blockIdx.x;
    const int b = nb >> 12, n = nb & 4095;
    const int pidx = (n & 127) * 32 + (n >> 7);
    const int t = threadIdx.x;                 // covers channels 8t..8t+7
    const float a = att[((size_t)(b * HEADS + (t >> 3))) * SEQ + pidx];
    const uint4 vu = *(const uint4*)(qkv + ((size_t)((b << 12) + pidx)) * QKVW +
                                     2 * DIM + 8 * t);
    const __half2* vh = (const __half2*)&vu;
    uint4 ou;
    __half2* oh = (__half2*)&ou;
#pragma unroll
    for (int i = 0; i < 4; i++) {
        const float2 v = __half22float2(vh[i]);
        oh[i] = __floats2half2_rn(a * v.x, a * v.y);
    }
    *(uint4*)(out + (size_t)nb * DIM + 8 * t) = ou;
}

// ---------------------------------------------------------------------------
// Launch
// ---------------------------------------------------------------------------
extern "C" void kernel_launch(void* const* d_in, const int* in_sizes, int n_in,
                              void* d_out, int out_size)
{
    const float* x     = (const float*)d_in[0];
    const float* ln1_g = (const float*)d_in[1];
    const float* ln1_b = (const float*)d_in[2];
    const float* wq    = (const float*)d_in[3];
    const float* wk    = (const float*)d_in[4];
    const float* wv    = (const float*)d_in[5];
    const float* wo    = (const float*)d_in[6];
    const float* bo    = (const float*)d_in[7];
    const float* ln2_g = (const float*)d_in[8];
    const float* ln2_b = (const float*)d_in[9];
    const float* w1    = (const float*)d_in[10];
    const float* b1    = (const float*)d_in[11];
    const float* w2    = (const float*)d_in[12];
    const float* b2    = (const float*)d_in[13];
    float* out = (float*)d_out;

    __half *h1, *qkv, *ao, *h2, *act, *wqkvT, *woT, *w1T, *w2T;
    float *x2, *dots;
    cudaGetSymbolAddress((void**)&h1,   g_h1);
    cudaGetSymbolAddress((void**)&qkv,  g_qkv);
    cudaGetSymbolAddress((void**)&ao,   g_ao);
    cudaGetSymbolAddress((void**)&x2,   g_x2);
    cudaGetSymbolAddress((void**)&h2,   g_h2);
    cudaGetSymbolAddress((void**)&dots, g_dot);
    cudaGetSymbolAddress((void**)&act,  g_act);
    cudaGetSymbolAddress((void**)&wqkvT,g_wqkvT);
    cudaGetSymbolAddress((void**)&woT,  g_woT);
    cudaGetSymbolAddress((void**)&w1T,  g_w1T);
    cudaGetSymbolAddress((void**)&w2T,  g_w2T);

    cudaFuncSetAttribute(gemm_fp16<0>, cudaFuncAttributeMaxDynamicSharedMemorySize, SMEM_DYN);
    cudaFuncSetAttribute(gemm_fp16<1>, cudaFuncAttributeMaxDynamicSharedMemorySize, SMEM_DYN);
    cudaFuncSetAttribute(gemm_fp16<2>, cudaFuncAttributeMaxDynamicSharedMemorySize, SMEM_DYN);

    // all 6 weight transposes in one launch (fp16 K-major B operands)
    transpose_all<<<12288, dim3(32, 8)>>>(wq, wk, wv, wo, w1, w2,
                                          wqkvT, woT, w1T, w2T);

    // 1. h1 = LN1(x)  (fp16)
    ln_kernel<<<ROWS, 256>>>(x, ln1_g, ln1_b, h1);
    // 2. qkv = h1 @ [wq|wk|wv]  (fp16 out)
    gemm_fp16<0><<<dim3(QKVW/128, ROWS/128), 128, SMEM_DYN>>>(
        h1, wqkvT, qkv, nullptr, nullptr, ROWS, QKVW, DIM);
    // 3-5. diagonal dots -> softmax over sequence -> permuted gather * V
    dots_kernel<<<ROWS, 128>>>(qkv, dots);
    softmax_kernel<<<BATCH * HEADS, 1024>>>(dots);
    gather_kernel<<<ROWS, 128>>>(qkv, dots, ao);
    // 6. x2 = x + ao @ wo + bo  (fp32 out)
    gemm_fp16<1><<<dim3(DIM/128, ROWS/128), 128, SMEM_DYN>>>(
        ao, woT, x2, x, bo, ROWS, DIM, DIM);
    // 7. h2 = LN2(x2)  (fp16)
    ln_kernel<<<ROWS, 256>>>(x2, ln2_g, ln2_b, h2);
    // 8. act = gelu(h2 @ w1 + b1)  (fp16 out)
    gemm_fp16<2><<<dim3(DFF/128, ROWS/128), 128, SMEM_DYN>>>(
        h2, w1T, act, nullptr, b1, ROWS, DFF, DIM);
    // 9. out = x2 + act @ w2 + b2  (fp32 out)
    gemm_fp16<1><<<dim3(DIM/128, ROWS/128), 128, SMEM_DYN>>>(
        act, w2T, out, x2, b2, ROWS, DIM, DFF);
}

// round 13
// speedup vs baseline: 1.5464x; 1.0054x over previous
#include <cuda_runtime.h>
#include <cuda_fp16.h>
#include <math.h>
#include <stdint.h>

// Problem dims (fixed)
#define BATCH 4
#define SEQ   4096
#define DIM   1024
#define HEADS 16
#define DFF   4096
#define ROWS  16384
#define QKVW  3072

// ---------------------------------------------------------------------------
// Scratch (device globals; no runtime allocation allowed)
// ---------------------------------------------------------------------------
__device__ __half g_h1  [ROWS*(size_t)DIM];
__device__ __half g_v   [ROWS*(size_t)DIM];
__device__ __half g_ao  [ROWS*(size_t)DIM];
__device__ float  g_x2  [ROWS*(size_t)DIM];
__device__ __half g_h2  [ROWS*(size_t)DIM];
__device__ float  g_dot [BATCH*HEADS*(size_t)SEQ];
__device__ __half g_act [ROWS*(size_t)DFF];
__device__ __half g_wqkvT[(size_t)QKVW*DIM];   // [3072][1024] K-major (N rows)
__device__ __half g_woT [(size_t)DIM*DIM];
__device__ __half g_w1T [(size_t)DFF*DIM];
__device__ __half g_w2T [(size_t)DIM*DFF];

// ---------------------------------------------------------------------------
// Helpers
// ---------------------------------------------------------------------------
__device__ __forceinline__ float gelu_exact(float x) {
    return 0.5f * x * (1.0f + erff(x * 0.70710678118654752f));
}
__device__ __forceinline__ uint32_t smem_u32(const void* p) {
    uint32_t a;
    asm("{ .reg .u64 t; cvta.to.shared.u64 t, %1; cvt.u32.u64 %0, t; }"
        : "=r"(a) : "l"(p));
    return a;
}
__device__ __forceinline__ void cp16(uint32_t dst, const void* src) {
    asm volatile("cp.async.cg.shared.global [%0], [%1], 16;" :: "r"(dst), "l"(src));
}
__device__ __forceinline__ void cp_commit() {
    asm volatile("cp.async.commit_group;" ::: "memory");
}
#define LDMX4(r0, r1, r2, r3, addr)                                           \
    asm volatile("ldmatrix.sync.aligned.m8n8.x4.shared.b16 {%0,%1,%2,%3}, [%4];" \
        : "=r"(r0), "=r"(r1), "=r"(r2), "=r"(r3) : "r"(addr))

// smem row: 32 k-halves data + 8 pad halves -> stride 40 halves (80B).
// Rows r within an 8-row ldmatrix tile hit banks (r*20)%32: all distinct.
#define OP_B     10240                     // bytes per operand tile (128*80)
#define STAGE_B  (2*OP_B)                  // 20480
#define STAGES   4
#define SMEM_DYN (STAGES*STAGE_B)          // 81920

// ---------------------------------------------------------------------------
// FP16 tensor-core GEMM: C[M,N] = A[M,K] @ Bt[N,K]^T  (A,Bt fp16)
//  EPI 0: store half           (C = __half*)
//  EPI 1: float store +res+bias (C = float*, res fp32)
//  EPI 2: half store gelu(+bias)
// CTA 128x128, 128 threads (4 warps 2x2, warp tile 64x64), k-chunk 32,
// 4-stage cp.async pipeline, ldmatrix fragment loads.  (R5/R9-proven config,
// UNCHANGED.)
// ---------------------------------------------------------------------------
template <int EPI>
__global__ __launch_bounds__(128, 2) void gemm_fp16(
    const __half* __restrict__ A, const __half* __restrict__ Bt,
    void* __restrict__ Cv, const float* __restrict__ res,
    const float* __restrict__ bias, int M, int N, int K)
{
    extern __shared__ char smc[];
    const uint32_t smb = smem_u32(smc);

    const int tid  = threadIdx.x;
    const int lane = tid & 31;
    const int wid  = tid >> 5;
    const int wm   = wid >> 1;
    const int wn   = wid & 1;
    const int g    = lane >> 2;
    const int t    = lane & 3;
    const int m0   = blockIdx.y << 7;
    const int n0   = blockIdx.x << 7;

    const uint32_t aoff =
        (uint32_t)(((wm * 64 + (lane & 7) + 8 * ((lane >> 3) & 1)) * 40 +
                    8 * (lane >> 4)) * 2);
    const uint32_t boff =
        (uint32_t)(OP_B + (((wn * 64 + (lane & 7) + 8 * (lane >> 4)) * 40 +
                            8 * ((lane >> 3) & 1)) * 2));

    uint32_t sA[4], sB[4];
    const __half* gA[4];
    const __half* gB[4];
#pragma unroll
    for (int j = 0; j < 4; j++) {
        const int gid = j * 128 + tid;
        const int row = gid >> 2, c = gid & 3;
        sA[j] = (uint32_t)(row * 80 + c * 16);
        sB[j] = (uint32_t)(OP_B + row * 80 + c * 16);
        gA[j] = A  + (size_t)(m0 + row) * K + c * 8;
        gB[j] = Bt + (size_t)(n0 + row) * K + c * 8;
    }

    float acc[4][8][4];
#pragma unroll
    for (int i = 0; i < 4; i++)
#pragma unroll
        for (int j = 0; j < 8; j++)
#pragma unroll
            for (int r = 0; r < 4; r++) acc[i][j][r] = 0.f;

    const int KT = K >> 5;

#pragma unroll
    for (int s = 0; s < STAGES; s++) {
        const uint32_t base = smb + s * STAGE_B;
        const int ko = s * 32;
#pragma unroll
        for (int j = 0; j < 4; j++) {
            cp16(base + sA[j], gA[j] + ko);
            cp16(base + sB[j], gB[j] + ko);
        }
        cp_commit();
    }

    for (int kt = 0; kt < KT; kt++) {
        asm volatile("cp.async.wait_group %0;" :: "n"(STAGES - 1) : "memory");
        __syncthreads();

        const uint32_t stg = smb + (kt % STAGES) * STAGE_B;

#pragma unroll
        for (int kc = 0; kc < 2; kc++) {
            const uint32_t kb = kc * 32;
            uint32_t af[4][4];
#pragma unroll
            for (int i = 0; i < 4; i++)
                LDMX4(af[i][0], af[i][1], af[i][2], af[i][3],
                      stg + aoff + i * 1280 + kb);
            uint32_t bf[8][2];
#pragma unroll
            for (int jj = 0; jj < 4; jj++)
                LDMX4(bf[2 * jj][0], bf[2 * jj][1],
                      bf[2 * jj + 1][0], bf[2 * jj + 1][1],
                      stg + boff + jj * 1280 + kb);
#pragma unroll
            for (int i = 0; i < 4; i++)
#pragma unroll
                for (int j = 0; j < 8; j++) {
                    asm volatile(
                        "mma.sync.aligned.m16n8k16.row.col.f32.f16.f16.f32 "
                        "{%0,%1,%2,%3}, {%4,%5,%6,%7}, {%8,%9}, {%0,%1,%2,%3};"
                        : "+f"(acc[i][j][0]), "+f"(acc[i][j][1]),
                          "+f"(acc[i][j][2]), "+f"(acc[i][j][3])
                        : "r"(af[i][0]), "r"(af[i][1]),
                          "r"(af[i][2]), "r"(af[i][3]),
                          "r"(bf[j][0]), "r"(bf[j][1]));
                }
        }
        __syncthreads();

        const int nk = kt + STAGES;
        if (nk < KT) {
            const uint32_t base = smb + (nk % STAGES) * STAGE_B;
            const int ko = nk * 32;
#pragma unroll
            for (int j = 0; j < 4; j++) {
                cp16(base + sA[j], gA[j] + ko);
                cp16(base + sB[j], gB[j] + ko);
            }
        }
        cp_commit();
    }

    // epilogue
#pragma unroll
    for (int j = 0; j < 8; j++) {
        const int col = n0 + wn * 64 + j * 8 + t * 2;
        float2 bv = make_float2(0.f, 0.f);
        if (EPI != 0) bv = *(const float2*)&bias[col];
#pragma unroll
        for (int i = 0; i < 4; i++) {
            const int row0 = m0 + wm * 64 + i * 16 + g;
#pragma unroll
            for (int h = 0; h < 2; h++) {
                const int r = row0 + 8 * h;
                const float a = acc[i][j][2 * h + 0];
                const float b = acc[i][j][2 * h + 1];
                if (EPI == 0) {
                    *(__half2*)((__half*)Cv + (size_t)r * N + col) =
                        __floats2half2_rn(a, b);
                } else if (EPI == 1) {
                    const float2 rv = *(const float2*)&res[(size_t)r * N + col];
                    float2 o;
                    o.x = a + rv.x + bv.x;
                    o.y = b + rv.y + bv.y;
                    *(float2*)((float*)Cv + (size_t)r * N + col) = o;
                } else {
                    *(__half2*)((__half*)Cv + (size_t)r * N + col) =
                        __floats2half2_rn(gelu_exact(a + bv.x),
                                          gelu_exact(b + bv.y));
                }
            }
        }
    }
}

// ---------------------------------------------------------------------------
// QK GEMM with fused diagonal dot (R13 change):
// CTA = (head, m-tile). B tile rows 0-63 = Q weights of head, 64-127 = K
// weights of head. Mainloop identical to proven gemm. Epilogue: stage fp32
// Q/K tiles in smem, each thread reduces one row's 64-channel dot, writes
// dots[b,h,r] * DH^-0.5 directly. Q/K never touch gmem.
// ---------------------------------------------------------------------------
__global__ __launch_bounds__(128, 2) void gemm_qk_dots(
    const __half* __restrict__ A, const __half* __restrict__ BtAll,
    float* __restrict__ dots, int K)
{
    extern __shared__ char smc[];
    const uint32_t smb = smem_u32(smc);

    const int tid  = threadIdx.x;
    const int lane = tid & 31;
    const int wid  = tid >> 5;
    const int wm   = wid >> 1;
    const int wn   = wid & 1;
    const int g    = lane >> 2;
    const int t    = lane & 3;
    const int head = blockIdx.x;
    const int m0   = blockIdx.y << 7;

    const uint32_t aoff =
        (uint32_t)(((wm * 64 + (lane & 7) + 8 * ((lane >> 3) & 1)) * 40 +
                    8 * (lane >> 4)) * 2);
    const uint32_t boff =
        (uint32_t)(OP_B + (((wn * 64 + (lane & 7) + 8 * (lane >> 4)) * 40 +
                            8 * ((lane >> 3) & 1)) * 2));

    uint32_t sA[4], sB[4];
    const __half* gA[4];
    const __half* gB[4];
#pragma unroll
    for (int j = 0; j < 4; j++) {
        const int gid = j * 128 + tid;
        const int row = gid >> 2, c = gid & 3;
        sA[j] = (uint32_t)(row * 80 + c * 16);
        sB[j] = (uint32_t)(OP_B + row * 80 + c * 16);
        gA[j] = A + (size_t)(m0 + row) * K + c * 8;
        const int wrow = (row < 64) ? (head * 64 + row)
                                    : (1024 + head * 64 + (row - 64));
        gB[j] = BtAll + (size_t)wrow * K + c * 8;
    }

    float acc[4][8][4];
#pragma unroll
    for (int i = 0; i < 4; i++)
#pragma unroll
        for (int j = 0; j < 8; j++)
#pragma unroll
            for (int r = 0; r < 4; r++) acc[i][j][r] = 0.f;

    const int KT = K >> 5;

#pragma unroll
    for (int s = 0; s < STAGES; s++) {
        const uint32_t base = smb + s * STAGE_B;
        const int ko = s * 32;
#pragma unroll
        for (int j = 0; j < 4; j++) {
            cp16(base + sA[j], gA[j] + ko);
            cp16(base + sB[j], gB[j] + ko);
        }
        cp_commit();
    }

    for (int kt = 0; kt < KT; kt++) {
        asm volatile("cp.async.wait_group %0;" :: "n"(STAGES - 1) : "memory");
        __syncthreads();

        const uint32_t stg = smb + (kt % STAGES) * STAGE_B;

#pragma unroll
        for (int kc = 0; kc < 2; kc++) {
            const uint32_t kb = kc * 32;
            uint32_t af[4][4];
#pragma unroll
            for (int i = 0; i < 4; i++)
                LDMX4(af[i][0], af[i][1], af[i][2], af[i][3],
                      stg + aoff + i * 1280 + kb);
            uint32_t bf[8][2];
#pragma unroll
            for (int jj = 0; jj < 4; jj++)
                LDMX4(bf[2 * jj][0], bf[2 * jj][1],
                      bf[2 * jj + 1][0], bf[2 * jj + 1][1],
                      stg + boff + jj * 1280 + kb);
#pragma unroll
            for (int i = 0; i < 4; i++)
#pragma unroll
                for (int j = 0; j < 8; j++) {
                    asm volatile(
                        "mma.sync.aligned.m16n8k16.row.col.f32.f16.f16.f32 "
                        "{%0,%1,%2,%3}, {%4,%5,%6,%7}, {%8,%9}, {%0,%1,%2,%3};"
                        : "+f"(acc[i][j][0]), "+f"(acc[i][j][1]),
                          "+f"(acc[i][j][2]), "+f"(acc[i][j][3])
                        : "r"(af[i][0]), "r"(af[i][1]),
                          "r"(af[i][2]), "r"(af[i][3]),
                          "r"(bf[j][0]), "r"(bf[j][1]));
                }
        }
        __syncthreads();

        const int nk = kt + STAGES;
        if (nk < KT) {
            const uint32_t base = smb + (nk % STAGES) * STAGE_B;
            const int ko = nk * 32;
#pragma unroll
            for (int j = 0; j < 4; j++) {
                cp16(base + sA[j], gA[j] + ko);
                cp16(base + sB[j], gB[j] + ko);
            }
        }
        cp_commit();
    }

    // fused-dot epilogue: drain pipeline, reuse stage smem as fp32 Q/K tiles
    asm volatile("cp.async.wait_group 0;" ::: "memory");
    __syncthreads();

    float* smQ = (float*)smc;            // [128][65]
    float* smK = smQ + 128 * 65;         // [128][65]  (total 66560 B < 81920)
    float* dst = (wn == 0) ? smQ : smK;
#pragma unroll
    for (int j = 0; j < 8; j++) {
        const int col = j * 8 + t * 2;   // 0..62
#pragma unroll
        for (int i = 0; i < 4; i++) {
            const int row0 = wm * 64 + i * 16 + g;
#pragma unroll
            for (int h = 0; h < 2; h++) {
                const int r = row0 + 8 * h;
                dst[r * 65 + col]     = acc[i][j][2 * h + 0];
                dst[r * 65 + col + 1] = acc[i][j][2 * h + 1];
            }
        }
    }
    __syncthreads();

    // thread tid reduces row tid: dot over 64 channels
    {
        const float* qr = smQ + tid * 65;
        const float* kr = smK + tid * 65;
        float s = 0.f;
#pragma unroll
        for (int c = 0; c < 64; c++) s += qr[c] * kr[c];
        const int m = m0 + tid;
        dots[((size_t)((m >> 12) * HEADS + head)) * SEQ + (m & 4095)] =
            s * 0.125f;
    }
}

// ---------------------------------------------------------------------------
// All 6 weight transposes in ONE launch.
// ---------------------------------------------------------------------------
__global__ __launch_bounds__(256) void transpose_all(
    const float* __restrict__ wq, const float* __restrict__ wk,
    const float* __restrict__ wv, const float* __restrict__ wo,
    const float* __restrict__ w1, const float* __restrict__ w2,
    __half* __restrict__ wqkvT, __half* __restrict__ woT,
    __half* __restrict__ w1T, __half* __restrict__ w2T)
{
    __shared__ float sh[32][33];
    const int tile = blockIdx.x;
    const float* in;
    __half* out;
    int R, C, cx, ry;
    if (tile < 4096) {
        const int job = tile >> 10, loc = tile & 1023;
        cx = loc & 31; ry = loc >> 5; R = 1024; C = 1024;
        if (job == 0)      { in = wq; out = wqkvT; }
        else if (job == 1) { in = wk; out = wqkvT + (size_t)1024 * 1024; }
        else if (job == 2) { in = wv; out = wqkvT + (size_t)2 * 1024 * 1024; }
        else               { in = wo; out = woT; }
    } else if (tile < 8192) {
        const int loc = tile - 4096;
        cx = loc & 127; ry = loc >> 7; R = 1024; C = 4096;
        in = w1; out = w1T;
    } else {
        const int loc = tile - 8192;
        cx = loc & 31; ry = loc >> 5; R = 4096; C = 1024;
        in = w2; out = w2T;
    }
    const int c0 = cx * 32, r0 = ry * 32;
    const int tx = threadIdx.x, ty = threadIdx.y;
#pragma unroll
    for (int j = 0; j < 4; j++)
        sh[ty + j * 8][tx] = in[(size_t)(r0 + ty + j * 8) * C + c0 + tx];
    __syncthreads();
#pragma unroll
    for (int j = 0; j < 4; j++)
        out[(size_t)(c0 + ty + j * 8) * R + r0 + tx] = __float2half(sh[tx][ty + j * 8]);
}

// ---------------------------------------------------------------------------
// LayerNorm -> fp16 output (feeds GEMM A)
// ---------------------------------------------------------------------------
__global__ __launch_bounds__(256) void ln_kernel(
    const float* __restrict__ x, const float* __restrict__ gam,
    const float* __restrict__ bet, __half* __restrict__ out)
{
    const int row = blockIdx.x;
    const float* xr = x + (size_t)row * DIM;
    float v[4];
    float s = 0.f, ss = 0.f;
#pragma unroll
    for (int i = 0; i < 4; i++) {
        v[i] = xr[threadIdx.x + i * 256];
        s += v[i]; ss += v[i] * v[i];
    }
#pragma unroll
    for (int o = 16; o; o >>= 1) {
        s  += __shfl_xor_sync(0xffffffffu, s, o);
        ss += __shfl_xor_sync(0xffffffffu, ss, o);
    }
    __shared__ float sh1[8], sh2[8];
    const int w = threadIdx.x >> 5, l = threadIdx.x & 31;
    if (l == 0) { sh1[w] = s; sh2[w] = ss; }
    __syncthreads();
    s = 0.f; ss = 0.f;
#pragma unroll
    for (int i = 0; i < 8; i++) { s += sh1[i]; ss += sh2[i]; }
    const float mu   = s * (1.0f / DIM);
    const float var  = ss * (1.0f / DIM) - mu * mu;
    const float rstd = rsqrtf(var + 1e-5f);
    __half* outr = out + (size_t)row * DIM;
#pragma unroll
    for (int i = 0; i < 4; i++) {
        int c = threadIdx.x + i * 256;
        outr[c] = __float2half((v[i] - mu) * rstd * gam[c] + bet[c]);
    }
}

__global__ __launch_bounds__(1024) void softmax_kernel(float* __restrict__ d)
{
    const int row = blockIdx.x;
    float4* p = (float4*)(d + (size_t)row * SEQ);
    float4 v = p[threadIdx.x];
    float m = fmaxf(fmaxf(v.x, v.y), fmaxf(v.z, v.w));
#pragma unroll
    for (int o = 16; o; o >>= 1) m = fmaxf(m, __shfl_xor_sync(0xffffffffu, m, o));
    __shared__ float sm[32];
    const int w = threadIdx.x >> 5, l = threadIdx.x & 31;
    if (l == 0) sm[w] = m;
    __syncthreads();
    m = sm[0];
#pragma unroll
    for (int i = 1; i < 32; i++) m = fmaxf(m, sm[i]);
    __syncthreads();
    float4 e;
    e.x = expf(v.x - m); e.y = expf(v.y - m);
    e.z = expf(v.z - m); e.w = expf(v.w - m);
    float s = e.x + e.y + e.z + e.w;
#pragma unroll
    for (int o = 16; o; o >>= 1) s += __shfl_xor_sync(0xffffffffu, s, o);
    if (l == 0) sm[w] = s;
    __syncthreads();
    s = 0.f;
#pragma unroll
    for (int i = 0; i < 32; i++) s += sm[i];
    const float inv = 1.0f / s;
    e.x *= inv; e.y *= inv; e.z *= inv; e.w *= inv;
    p[threadIdx.x] = e;
}

// attn_out[b,n',c] = att[b, c/64, p(n')] * V[b, p(n'), c]; p(n')=(n'%128)*32+n'/128
// 16B vector load + 16B vector store per thread. V now in dedicated buffer.
__global__ __launch_bounds__(128) void gather_kernel(
    const __half* __restrict__ v, const float* __restrict__ att,
    __half* __restrict__ out)
{
    const int nb = blockIdx.x;
    const int b = nb >> 12, n = nb & 4095;
    const int pidx = (n & 127) * 32 + (n >> 7);
    const int t = threadIdx.x;                 // covers channels 8t..8t+7
    const float a = att[((size_t)(b * HEADS + (t >> 3))) * SEQ + pidx];
    const uint4 vu = *(const uint4*)(v + (size_t)((b << 12) + pidx) * DIM + 8 * t);
    const __half2* vh = (const __half2*)&vu;
    uint4 ou;
    __half2* oh = (__half2*)&ou;
#pragma unroll
    for (int i = 0; i < 4; i++) {
        const float2 vv = __half22float2(vh[i]);
        oh[i] = __floats2half2_rn(a * vv.x, a * vv.y);
    }
    *(uint4*)(out + (size_t)nb * DIM + 8 * t) = ou;
}

// ---------------------------------------------------------------------------
// Launch
// ---------------------------------------------------------------------------
extern "C" void kernel_launch(void* const* d_in, const int* in_sizes, int n_in,
                              void* d_out, int out_size)
{
    const float* x     = (const float*)d_in[0];
    const float* ln1_g = (const float*)d_in[1];
    const float* ln1_b = (const float*)d_in[2];
    const float* wq    = (const float*)d_in[3];
    const float* wk    = (const float*)d_in[4];
    const float* wv    = (const float*)d_in[5];
    const float* wo    = (const float*)d_in[6];
    const float* bo    = (const float*)d_in[7];
    const float* ln2_g = (const float*)d_in[8];
    const float* ln2_b = (const float*)d_in[9];
    const float* w1    = (const float*)d_in[10];
    const float* b1    = (const float*)d_in[11];
    const float* w2    = (const float*)d_in[12];
    const float* b2    = (const float*)d_in[13];
    float* out = (float*)d_out;

    __half *h1, *v, *ao, *h2, *act, *wqkvT, *woT, *w1T, *w2T;
    float *x2, *dots;
    cudaGetSymbolAddress((void**)&h1,   g_h1);
    cudaGetSymbolAddress((void**)&v,    g_v);
    cudaGetSymbolAddress((void**)&ao,   g_ao);
    cudaGetSymbolAddress((void**)&x2,   g_x2);
    cudaGetSymbolAddress((void**)&h2,   g_h2);
    cudaGetSymbolAddress((void**)&dots, g_dot);
    cudaGetSymbolAddress((void**)&act,  g_act);
    cudaGetSymbolAddress((void**)&wqkvT,g_wqkvT);
    cudaGetSymbolAddress((void**)&woT,  g_woT);
    cudaGetSymbolAddress((void**)&w1T,  g_w1T);
    cudaGetSymbolAddress((void**)&w2T,  g_w2T);

    cudaFuncSetAttribute(gemm_fp16<0>, cudaFuncAttributeMaxDynamicSharedMemorySize, SMEM_DYN);
    cudaFuncSetAttribute(gemm_fp16<1>, cudaFuncAttributeMaxDynamicSharedMemorySize, SMEM_DYN);
    cudaFuncSetAttribute(gemm_fp16<2>, cudaFuncAttributeMaxDynamicSharedMemorySize, SMEM_DYN);
    cudaFuncSetAttribute(gemm_qk_dots, cudaFuncAttributeMaxDynamicSharedMemorySize, SMEM_DYN);

    // all 6 weight transposes in one launch (fp16 K-major B operands)
    transpose_all<<<12288, dim3(32, 8)>>>(wq, wk, wv, wo, w1, w2,
                                          wqkvT, woT, w1T, w2T);

    // 1. h1 = LN1(x)  (fp16)
    ln_kernel<<<ROWS, 256>>>(x, ln1_g, ln1_b, h1);
    // 2a. fused QK GEMM + diagonal dot -> dots (Q,K never hit gmem)
    gemm_qk_dots<<<dim3(HEADS, ROWS/128), 128, SMEM_DYN>>>(h1, wqkvT, dots, DIM);
    // 2b. V = h1 @ wv  (fp16 out)
    gemm_fp16<0><<<dim3(DIM/128, ROWS/128), 128, SMEM_DYN>>>(
        h1, wqkvT + (size_t)2048 * DIM, v, nullptr, nullptr, ROWS, DIM, DIM);
    // 3-4. softmax over sequence -> permuted gather * V
    softmax_kernel<<<BATCH * HEADS, 1024>>>(dots);
    gather_kernel<<<ROWS, 128>>>(v, dots, ao);
    // 5. x2 = x + ao @ wo + bo  (fp32 out)
    gemm_fp16<1><<<dim3(DIM/128, ROWS/128), 128, SMEM_DYN>>>(
        ao, woT, x2, x, bo, ROWS, DIM, DIM);
    // 6. h2 = LN2(x2)  (fp16)
    ln_kernel<<<ROWS, 256>>>(x2, ln2_g, ln2_b, h2);
    // 7. act = gelu(h2 @ w1 + b1)  (fp16 out)
    gemm_fp16<2><<<dim3(DFF/128, ROWS/128), 128, SMEM_DYN>>>(
        h2, w1T, act, nullptr, b1, ROWS, DFF, DIM);
    // 8. out = x2 + act @ w2 + b2  (fp32 out)
    gemm_fp16<1><<<dim3(DIM/128, ROWS/128), 128, SMEM_DYN>>>(
        act, w2T, out, x2, b2, ROWS, DIM, DFF);
}

// round 14
// speedup vs baseline: 1.5606x; 1.0092x over previous
#include <cuda_runtime.h>
#include <cuda_fp16.h>
#include <math.h>
#include <stdint.h>

// Problem dims (fixed)
#define BATCH 4
#define SEQ   4096
#define DIM   1024
#define HEADS 16
#define DFF   4096
#define ROWS  16384
#define QKVW  3072

// ---------------------------------------------------------------------------
// Scratch (device globals; no runtime allocation allowed)
// ---------------------------------------------------------------------------
__device__ __half g_h1  [ROWS*(size_t)DIM];
__device__ __half g_ao  [ROWS*(size_t)DIM];
__device__ float  g_x2  [ROWS*(size_t)DIM];
__device__ __half g_h2  [ROWS*(size_t)DIM];
__device__ float  g_dot [BATCH*HEADS*(size_t)SEQ];
__device__ __half g_act [ROWS*(size_t)DFF];
__device__ __half g_wqkvT[(size_t)QKVW*DIM];   // [3072][1024] K-major (N rows)
__device__ __half g_woT [(size_t)DIM*DIM];
__device__ __half g_w1T [(size_t)DFF*DIM];
__device__ __half g_w2T [(size_t)DIM*DFF];

// ---------------------------------------------------------------------------
// Helpers
// ---------------------------------------------------------------------------
__device__ __forceinline__ float gelu_exact(float x) {
    return 0.5f * x * (1.0f + erff(x * 0.70710678118654752f));
}
__device__ __forceinline__ uint32_t smem_u32(const void* p) {
    uint32_t a;
    asm("{ .reg .u64 t; cvta.to.shared.u64 t, %1; cvt.u32.u64 %0, t; }"
        : "=r"(a) : "l"(p));
    return a;
}
__device__ __forceinline__ void cp16(uint32_t dst, const void* src) {
    asm volatile("cp.async.cg.shared.global [%0], [%1], 16;" :: "r"(dst), "l"(src));
}
__device__ __forceinline__ void cp_commit() {
    asm volatile("cp.async.commit_group;" ::: "memory");
}
#define LDMX4(r0, r1, r2, r3, addr)                                           \
    asm volatile("ldmatrix.sync.aligned.m8n8.x4.shared.b16 {%0,%1,%2,%3}, [%4];" \
        : "=r"(r0), "=r"(r1), "=r"(r2), "=r"(r3) : "r"(addr))

// smem row: 32 k-halves data + 8 pad halves -> stride 40 halves (80B).
// Rows r within an 8-row ldmatrix tile hit banks (r*20)%32: all distinct.
#define OP_B     10240                     // bytes per operand tile (128*80)
#define STAGE_B  (2*OP_B)                  // 20480
#define STAGES   4
#define SMEM_DYN (STAGES*STAGE_B)          // 81920

// ---------------------------------------------------------------------------
// FP16 tensor-core GEMM: C[M,N] = A[M,K] @ Bt[N,K]^T  (A,Bt fp16)
//  EPI 0: store half             (C = __half*)
//  EPI 1: float store +res+bias  (C = float*, res fp32)
//  EPI 2: half store gelu(+bias)
//  EPI 3: fused attention gather (res = dots; scale rows by att, write to
//         permuted row n' = (m%32)*128 + m/32 of the same batch, half out)
// CTA 128x128, 128 threads (4 warps 2x2, warp tile 64x64), k-chunk 32,
// 4-stage cp.async pipeline, ldmatrix fragment loads.  (Mainloop = proven
// R5/R9 config, UNCHANGED.)
// ---------------------------------------------------------------------------
template <int EPI>
__global__ __launch_bounds__(128, 2) void gemm_fp16(
    const __half* __restrict__ A, const __half* __restrict__ Bt,
    void* __restrict__ Cv, const float* __restrict__ res,
    const float* __restrict__ bias, int M, int N, int K)
{
    extern __shared__ char smc[];
    const uint32_t smb = smem_u32(smc);

    const int tid  = threadIdx.x;
    const int lane = tid & 31;
    const int wid  = tid >> 5;
    const int wm   = wid >> 1;
    const int wn   = wid & 1;
    const int g    = lane >> 2;
    const int t    = lane & 3;
    const int m0   = blockIdx.y << 7;
    const int n0   = blockIdx.x << 7;

    const uint32_t aoff =
        (uint32_t)(((wm * 64 + (lane & 7) + 8 * ((lane >> 3) & 1)) * 40 +
                    8 * (lane >> 4)) * 2);
    const uint32_t boff =
        (uint32_t)(OP_B + (((wn * 64 + (lane & 7) + 8 * (lane >> 4)) * 40 +
                            8 * ((lane >> 3) & 1)) * 2));

    uint32_t sA[4], sB[4];
    const __half* gA[4];
    const __half* gB[4];
#pragma unroll
    for (int j = 0; j < 4; j++) {
        const int gid = j * 128 + tid;
        const int row = gid >> 2, c = gid & 3;
        sA[j] = (uint32_t)(row * 80 + c * 16);
        sB[j] = (uint32_t)(OP_B + row * 80 + c * 16);
        gA[j] = A  + (size_t)(m0 + row) * K + c * 8;
        gB[j] = Bt + (size_t)(n0 + row) * K + c * 8;
    }

    float acc[4][8][4];
#pragma unroll
    for (int i = 0; i < 4; i++)
#pragma unroll
        for (int j = 0; j < 8; j++)
#pragma unroll
            for (int r = 0; r < 4; r++) acc[i][j][r] = 0.f;

    const int KT = K >> 5;

#pragma unroll
    for (int s = 0; s < STAGES; s++) {
        const uint32_t base = smb + s * STAGE_B;
        const int ko = s * 32;
#pragma unroll
        for (int j = 0; j < 4; j++) {
            cp16(base + sA[j], gA[j] + ko);
            cp16(base + sB[j], gB[j] + ko);
        }
        cp_commit();
    }

    for (int kt = 0; kt < KT; kt++) {
        asm volatile("cp.async.wait_group %0;" :: "n"(STAGES - 1) : "memory");
        __syncthreads();

        const uint32_t stg = smb + (kt % STAGES) * STAGE_B;

#pragma unroll
        for (int kc = 0; kc < 2; kc++) {
            const uint32_t kb = kc * 32;
            uint32_t af[4][4];
#pragma unroll
            for (int i = 0; i < 4; i++)
                LDMX4(af[i][0], af[i][1], af[i][2], af[i][3],
                      stg + aoff + i * 1280 + kb);
            uint32_t bf[8][2];
#pragma unroll
            for (int jj = 0; jj < 4; jj++)
                LDMX4(bf[2 * jj][0], bf[2 * jj][1],
                      bf[2 * jj + 1][0], bf[2 * jj + 1][1],
                      stg + boff + jj * 1280 + kb);
#pragma unroll
            for (int i = 0; i < 4; i++)
#pragma unroll
                for (int j = 0; j < 8; j++) {
                    asm volatile(
                        "mma.sync.aligned.m16n8k16.row.col.f32.f16.f16.f32 "
                        "{%0,%1,%2,%3}, {%4,%5,%6,%7}, {%8,%9}, {%0,%1,%2,%3};"
                        : "+f"(acc[i][j][0]), "+f"(acc[i][j][1]),
                          "+f"(acc[i][j][2]), "+f"(acc[i][j][3])
                        : "r"(af[i][0]), "r"(af[i][1]),
                          "r"(af[i][2]), "r"(af[i][3]),
                          "r"(bf[j][0]), "r"(bf[j][1]));
                }
        }
        __syncthreads();

        const int nk = kt + STAGES;
        if (nk < KT) {
            const uint32_t base = smb + (nk % STAGES) * STAGE_B;
            const int ko = nk * 32;
#pragma unroll
            for (int j = 0; j < 4; j++) {
                cp16(base + sA[j], gA[j] + ko);
                cp16(base + sB[j], gB[j] + ko);
            }
        }
        cp_commit();
    }

    if (EPI == 3) {
        // fused gather epilogue: scale rows by att, stage half tile in smem,
        // store permuted rows contiguously.
        asm volatile("cp.async.wait_group 0;" ::: "memory");
        __syncthreads();
        const float* att = res;
        const int head = (n0 >> 6) + wn;           // constant per thread
        __half* st = (__half*)smc;                 // [128][136] halves
#pragma unroll
        for (int i = 0; i < 4; i++)
#pragma unroll
            for (int h = 0; h < 2; h++) {
                const int rl = wm * 64 + i * 16 + g + 8 * h;
                const int m = m0 + rl;
                const float a =
                    att[((size_t)((m >> 12) * HEADS + head)) * SEQ + (m & 4095)];
#pragma unroll
                for (int j = 0; j < 8; j++) {
                    const int col = wn * 64 + j * 8 + t * 2;
                    st[rl * 136 + col] =
                        __float2half(a * acc[i][j][2 * h + 0]);
                    st[rl * 136 + col + 1] =
                        __float2half(a * acc[i][j][2 * h + 1]);
                }
            }
        __syncthreads();
        const int cchunk = (tid & 15) * 8;         // 16 chunks of 8 cols
#pragma unroll
        for (int p = 0; p < 16; p++) {
            const int rl = p * 8 + (tid >> 4);
            const int m = m0 + rl;
            const int b = m >> 12, ml = m & 4095;
            const int np = (ml & 31) * 128 + (ml >> 5);   // inverse permutation
            const uint4 ou = *(const uint4*)(st + rl * 136 + cchunk);
            *(uint4*)((__half*)Cv + ((size_t)(b << 12) + np) * N + n0 + cchunk) = ou;
        }
        return;
    }

    // epilogue (EPI 0/1/2)
#pragma unroll
    for (int j = 0; j < 8; j++) {
        const int col = n0 + wn * 64 + j * 8 + t * 2;
        float2 bv = make_float2(0.f, 0.f);
        if (EPI == 1 || EPI == 2) bv = *(const float2*)&bias[col];
#pragma unroll
        for (int i = 0; i < 4; i++) {
            const int row0 = m0 + wm * 64 + i * 16 + g;
#pragma unroll
            for (int h = 0; h < 2; h++) {
                const int r = row0 + 8 * h;
                const float a = acc[i][j][2 * h + 0];
                const float b = acc[i][j][2 * h + 1];
                if (EPI == 0) {
                    *(__half2*)((__half*)Cv + (size_t)r * N + col) =
                        __floats2half2_rn(a, b);
                } else if (EPI == 1) {
                    const float2 rv = *(const float2*)&res[(size_t)r * N + col];
                    float2 o;
                    o.x = a + rv.x + bv.x;
                    o.y = b + rv.y + bv.y;
                    *(float2*)((float*)Cv + (size_t)r * N + col) = o;
                } else {
                    *(__half2*)((__half*)Cv + (size_t)r * N + col) =
                        __floats2half2_rn(gelu_exact(a + bv.x),
                                          gelu_exact(b + bv.y));
                }
            }
        }
    }
}

// ---------------------------------------------------------------------------
// QK GEMM with fused diagonal dot (R13-proven): CTA = (head, m-tile).
// B rows 0-63 = Q weights of head, 64-127 = K weights. Epilogue reduces the
// per-row 64-channel Q·K dot and writes dots directly; Q/K never hit gmem.
// ---------------------------------------------------------------------------
__global__ __launch_bounds__(128, 2) void gemm_qk_dots(
    const __half* __restrict__ A, const __half* __restrict__ BtAll,
    float* __restrict__ dots, int K)
{
    extern __shared__ char smc[];
    const uint32_t smb = smem_u32(smc);

    const int tid  = threadIdx.x;
    const int lane = tid & 31;
    const int wid  = tid >> 5;
    const int wm   = wid >> 1;
    const int wn   = wid & 1;
    const int g    = lane >> 2;
    const int t    = lane & 3;
    const int head = blockIdx.x;
    const int m0   = blockIdx.y << 7;

    const uint32_t aoff =
        (uint32_t)(((wm * 64 + (lane & 7) + 8 * ((lane >> 3) & 1)) * 40 +
                    8 * (lane >> 4)) * 2);
    const uint32_t boff =
        (uint32_t)(OP_B + (((wn * 64 + (lane & 7) + 8 * (lane >> 4)) * 40 +
                            8 * ((lane >> 3) & 1)) * 2));

    uint32_t sA[4], sB[4];
    const __half* gA[4];
    const __half* gB[4];
#pragma unroll
    for (int j = 0; j < 4; j++) {
        const int gid = j * 128 + tid;
        const int row = gid >> 2, c = gid & 3;
        sA[j] = (uint32_t)(row * 80 + c * 16);
        sB[j] = (uint32_t)(OP_B + row * 80 + c * 16);
        gA[j] = A + (size_t)(m0 + row) * K + c * 8;
        const int wrow = (row < 64) ? (head * 64 + row)
                                    : (1024 + head * 64 + (row - 64));
        gB[j] = BtAll + (size_t)wrow * K + c * 8;
    }

    float acc[4][8][4];
#pragma unroll
    for (int i = 0; i < 4; i++)
#pragma unroll
        for (int j = 0; j < 8; j++)
#pragma unroll
            for (int r = 0; r < 4; r++) acc[i][j][r] = 0.f;

    const int KT = K >> 5;

#pragma unroll
    for (int s = 0; s < STAGES; s++) {
        const uint32_t base = smb + s * STAGE_B;
        const int ko = s * 32;
#pragma unroll
        for (int j = 0; j < 4; j++) {
            cp16(base + sA[j], gA[j] + ko);
            cp16(base + sB[j], gB[j] + ko);
        }
        cp_commit();
    }

    for (int kt = 0; kt < KT; kt++) {
        asm volatile("cp.async.wait_group %0;" :: "n"(STAGES - 1) : "memory");
        __syncthreads();

        const uint32_t stg = smb + (kt % STAGES) * STAGE_B;

#pragma unroll
        for (int kc = 0; kc < 2; kc++) {
            const uint32_t kb = kc * 32;
            uint32_t af[4][4];
#pragma unroll
            for (int i = 0; i < 4; i++)
                LDMX4(af[i][0], af[i][1], af[i][2], af[i][3],
                      stg + aoff + i * 1280 + kb);
            uint32_t bf[8][2];
#pragma unroll
            for (int jj = 0; jj < 4; jj++)
                LDMX4(bf[2 * jj][0], bf[2 * jj][1],
                      bf[2 * jj + 1][0], bf[2 * jj + 1][1],
                      stg + boff + jj * 1280 + kb);
#pragma unroll
            for (int i = 0; i < 4; i++)
#pragma unroll
                for (int j = 0; j < 8; j++) {
                    asm volatile(
                        "mma.sync.aligned.m16n8k16.row.col.f32.f16.f16.f32 "
                        "{%0,%1,%2,%3}, {%4,%5,%6,%7}, {%8,%9}, {%0,%1,%2,%3};"
                        : "+f"(acc[i][j][0]), "+f"(acc[i][j][1]),
                          "+f"(acc[i][j][2]), "+f"(acc[i][j][3])
                        : "r"(af[i][0]), "r"(af[i][1]),
                          "r"(af[i][2]), "r"(af[i][3]),
                          "r"(bf[j][0]), "r"(bf[j][1]));
                }
        }
        __syncthreads();

        const int nk = kt + STAGES;
        if (nk < KT) {
            const uint32_t base = smb + (nk % STAGES) * STAGE_B;
            const int ko = nk * 32;
#pragma unroll
            for (int j = 0; j < 4; j++) {
                cp16(base + sA[j], gA[j] + ko);
                cp16(base + sB[j], gB[j] + ko);
            }
        }
        cp_commit();
    }

    // fused-dot epilogue: drain pipeline, reuse stage smem as fp32 Q/K tiles
    asm volatile("cp.async.wait_group 0;" ::: "memory");
    __syncthreads();

    float* smQ = (float*)smc;            // [128][65]
    float* smK = smQ + 128 * 65;         // [128][65]  (total 66560 B < 81920)
    float* dst = (wn == 0) ? smQ : smK;
#pragma unroll
    for (int j = 0; j < 8; j++) {
        const int col = j * 8 + t * 2;   // 0..62
#pragma unroll
        for (int i = 0; i < 4; i++) {
            const int row0 = wm * 64 + i * 16 + g;
#pragma unroll
            for (int h = 0; h < 2; h++) {
                const int r = row0 + 8 * h;
                dst[r * 65 + col]     = acc[i][j][2 * h + 0];
                dst[r * 65 + col + 1] = acc[i][j][2 * h + 1];
            }
        }
    }
    __syncthreads();

    {
        const float* qr = smQ + tid * 65;
        const float* kr = smK + tid * 65;
        float s = 0.f;
#pragma unroll
        for (int c = 0; c < 64; c++) s += qr[c] * kr[c];
        const int m = m0 + tid;
        dots[((size_t)((m >> 12) * HEADS + head)) * SEQ + (m & 4095)] =
            s * 0.125f;
    }
}

// ---------------------------------------------------------------------------
// All 6 weight transposes in ONE launch.
// ---------------------------------------------------------------------------
__global__ __launch_bounds__(256) void transpose_all(
    const float* __restrict__ wq, const float* __restrict__ wk,
    const float* __restrict__ wv, const float* __restrict__ wo,
    const float* __restrict__ w1, const float* __restrict__ w2,
    __half* __restrict__ wqkvT, __half* __restrict__ woT,
    __half* __restrict__ w1T, __half* __restrict__ w2T)
{
    __shared__ float sh[32][33];
    const int tile = blockIdx.x;
    const float* in;
    __half* out;
    int R, C, cx, ry;
    if (tile < 4096) {
        const int job = tile >> 10, loc = tile & 1023;
        cx = loc & 31; ry = loc >> 5; R = 1024; C = 1024;
        if (job == 0)      { in = wq; out = wqkvT; }
        else if (job == 1) { in = wk; out = wqkvT + (size_t)1024 * 1024; }
        else if (job == 2) { in = wv; out = wqkvT + (size_t)2 * 1024 * 1024; }
        else               { in = wo; out = woT; }
    } else if (tile < 8192) {
        const int loc = tile - 4096;
        cx = loc & 127; ry = loc >> 7; R = 1024; C = 4096;
        in = w1; out = w1T;
    } else {
        const int loc = tile - 8192;
        cx = loc & 31; ry = loc >> 5; R = 4096; C = 1024;
        in = w2; out = w2T;
    }
    const int c0 = cx * 32, r0 = ry * 32;
    const int tx = threadIdx.x, ty = threadIdx.y;
#pragma unroll
    for (int j = 0; j < 4; j++)
        sh[ty + j * 8][tx] = in[(size_t)(r0 + ty + j * 8) * C + c0 + tx];
    __syncthreads();
#pragma unroll
    for (int j = 0; j < 4; j++)
        out[(size_t)(c0 + ty + j * 8) * R + r0 + tx] = __float2half(sh[tx][ty + j * 8]);
}

// ---------------------------------------------------------------------------
// LayerNorm -> fp16 output (feeds GEMM A)
// ---------------------------------------------------------------------------
__global__ __launch_bounds__(256) void ln_kernel(
    const float* __restrict__ x, const float* __restrict__ gam,
    const float* __restrict__ bet, __half* __restrict__ out)
{
    const int row = blockIdx.x;
    const float* xr = x + (size_t)row * DIM;
    float v[4];
    float s = 0.f, ss = 0.f;
#pragma unroll
    for (int i = 0; i < 4; i++) {
        v[i] = xr[threadIdx.x + i * 256];
        s += v[i]; ss += v[i] * v[i];
    }
#pragma unroll
    for (int o = 16; o; o >>= 1) {
        s  += __shfl_xor_sync(0xffffffffu, s, o);
        ss += __shfl_xor_sync(0xffffffffu, ss, o);
    }
    __shared__ float sh1[8], sh2[8];
    const int w = threadIdx.x >> 5, l = threadIdx.x & 31;
    if (l == 0) { sh1[w] = s; sh2[w] = ss; }
    __syncthreads();
    s = 0.f; ss = 0.f;
#pragma unroll
    for (int i = 0; i < 8; i++) { s += sh1[i]; ss += sh2[i]; }
    const float mu   = s * (1.0f / DIM);
    const float var  = ss * (1.0f / DIM) - mu * mu;
    const float rstd = rsqrtf(var + 1e-5f);
    __half* outr = out + (size_t)row * DIM;
#pragma unroll
    for (int i = 0; i < 4; i++) {
        int c = threadIdx.x + i * 256;
        outr[c] = __float2half((v[i] - mu) * rstd * gam[c] + bet[c]);
    }
}

__global__ __launch_bounds__(1024) void softmax_kernel(float* __restrict__ d)
{
    const int row = blockIdx.x;
    float4* p = (float4*)(d + (size_t)row * SEQ);
    float4 v = p[threadIdx.x];
    float m = fmaxf(fmaxf(v.x, v.y), fmaxf(v.z, v.w));
#pragma unroll
    for (int o = 16; o; o >>= 1) m = fmaxf(m, __shfl_xor_sync(0xffffffffu, m, o));
    __shared__ float sm[32];
    const int w = threadIdx.x >> 5, l = threadIdx.x & 31;
    if (l == 0) sm[w] = m;
    __syncthreads();
    m = sm[0];
#pragma unroll
    for (int i = 1; i < 32; i++) m = fmaxf(m, sm[i]);
    __syncthreads();
    float4 e;
    e.x = expf(v.x - m); e.y = expf(v.y - m);
    e.z = expf(v.z - m); e.w = expf(v.w - m);
    float s = e.x + e.y + e.z + e.w;
#pragma unroll
    for (int o = 16; o; o >>= 1) s += __shfl_xor_sync(0xffffffffu, s, o);
    if (l == 0) sm[w] = s;
    __syncthreads();
    s = 0.f;
#pragma unroll
    for (int i = 0; i < 32; i++) s += sm[i];
    const float inv = 1.0f / s;
    e.x *= inv; e.y *= inv; e.z *= inv; e.w *= inv;
    p[threadIdx.x] = e;
}

// ---------------------------------------------------------------------------
// Launch
// ---------------------------------------------------------------------------
extern "C" void kernel_launch(void* const* d_in, const int* in_sizes, int n_in,
                              void* d_out, int out_size)
{
    const float* x     = (const float*)d_in[0];
    const float* ln1_g = (const float*)d_in[1];
    const float* ln1_b = (const float*)d_in[2];
    const float* wq    = (const float*)d_in[3];
    const float* wk    = (const float*)d_in[4];
    const float* wv    = (const float*)d_in[5];
    const float* wo    = (const float*)d_in[6];
    const float* bo    = (const float*)d_in[7];
    const float* ln2_g = (const float*)d_in[8];
    const float* ln2_b = (const float*)d_in[9];
    const float* w1    = (const float*)d_in[10];
    const float* b1    = (const float*)d_in[11];
    const float* w2    = (const float*)d_in[12];
    const float* b2    = (const float*)d_in[13];
    float* out = (float*)d_out;

    __half *h1, *ao, *h2, *act, *wqkvT, *woT, *w1T, *w2T;
    float *x2, *dots;
    cudaGetSymbolAddress((void**)&h1,   g_h1);
    cudaGetSymbolAddress((void**)&ao,   g_ao);
    cudaGetSymbolAddress((void**)&x2,   g_x2);
    cudaGetSymbolAddress((void**)&h2,   g_h2);
    cudaGetSymbolAddress((void**)&dots, g_dot);
    cudaGetSymbolAddress((void**)&act,  g_act);
    cudaGetSymbolAddress((void**)&wqkvT,g_wqkvT);
    cudaGetSymbolAddress((void**)&woT,  g_woT);
    cudaGetSymbolAddress((void**)&w1T,  g_w1T);
    cudaGetSymbolAddress((void**)&w2T,  g_w2T);

    cudaFuncSetAttribute(gemm_fp16<0>, cudaFuncAttributeMaxDynamicSharedMemorySize, SMEM_DYN);
    cudaFuncSetAttribute(gemm_fp16<1>, cudaFuncAttributeMaxDynamicSharedMemorySize, SMEM_DYN);
    cudaFuncSetAttribute(gemm_fp16<2>, cudaFuncAttributeMaxDynamicSharedMemorySize, SMEM_DYN);
    cudaFuncSetAttribute(gemm_fp16<3>, cudaFuncAttributeMaxDynamicSharedMemorySize, SMEM_DYN);
    cudaFuncSetAttribute(gemm_qk_dots, cudaFuncAttributeMaxDynamicSharedMemorySize, SMEM_DYN);

    // all 6 weight transposes in one launch (fp16 K-major B operands)
    transpose_all<<<12288, dim3(32, 8)>>>(wq, wk, wv, wo, w1, w2,
                                          wqkvT, woT, w1T, w2T);

    // 1. h1 = LN1(x)  (fp16)
    ln_kernel<<<ROWS, 256>>>(x, ln1_g, ln1_b, h1);
    // 2. fused QK GEMM + diagonal dot -> dots (Q,K never hit gmem)
    gemm_qk_dots<<<dim3(HEADS, ROWS/128), 128, SMEM_DYN>>>(h1, wqkvT, dots, DIM);
    // 3. softmax over sequence per (b,h)
    softmax_kernel<<<BATCH * HEADS, 1024>>>(dots);
    // 4. V GEMM with fused gather epilogue: ao[b,n',c] = att*V, V never hits gmem
    gemm_fp16<3><<<dim3(DIM/128, ROWS/128), 128, SMEM_DYN>>>(
        h1, wqkvT + (size_t)2048 * DIM, ao, dots, nullptr, ROWS, DIM, DIM);
    // 5. x2 = x + ao @ wo + bo  (fp32 out)
    gemm_fp16<1><<<dim3(DIM/128, ROWS/128), 128, SMEM_DYN>>>(
        ao, woT, x2, x, bo, ROWS, DIM, DIM);
    // 6. h2 = LN2(x2)  (fp16)
    ln_kernel<<<ROWS, 256>>>(x2, ln2_g, ln2_b, h2);
    // 7. act = gelu(h2 @ w1 + b1)  (fp16 out)
    gemm_fp16<2><<<dim3(DFF/128, ROWS/128), 128, SMEM_DYN>>>(
        h2, w1T, act, nullptr, b1, ROWS, DFF, DIM);
    // 8. out = x2 + act @ w2 + b2  (fp32 out)
    gemm_fp16<1><<<dim3(DIM/128, ROWS/128), 128, SMEM_DYN>>>(
        act, w2T, out, x2, b2, ROWS, DIM, DFF);
}

// round 16
// speedup vs baseline: 1.5667x; 1.0039x over previous
#include <cuda_runtime.h>
#include <cuda_fp16.h>
#include <math.h>
#include <stdint.h>

// Problem dims (fixed)
#define BATCH 4
#define SEQ   4096
#define DIM   1024
#define HEADS 16
#define DFF   4096
#define ROWS  16384
#define QKVW  3072

// ---------------------------------------------------------------------------
// Scratch (device globals; no runtime allocation allowed)
// ---------------------------------------------------------------------------
__device__ __half g_h1  [ROWS*(size_t)DIM];
__device__ __half g_ao  [ROWS*(size_t)DIM];
__device__ float  g_x2  [ROWS*(size_t)DIM];
__device__ __half g_h2  [ROWS*(size_t)DIM];
__device__ float  g_dot [BATCH*HEADS*(size_t)SEQ];
__device__ __half g_act [ROWS*(size_t)DFF];
__device__ __half g_wqkvT[(size_t)QKVW*DIM];   // [3072][1024] K-major (N rows)
__device__ __half g_woT [(size_t)DIM*DIM];
__device__ __half g_w1T [(size_t)DFF*DIM];
__device__ __half g_w2T [(size_t)DIM*DFF];

// ---------------------------------------------------------------------------
// Helpers
// ---------------------------------------------------------------------------
__device__ __forceinline__ float gelu_exact(float x) {
    return 0.5f * x * (1.0f + erff(x * 0.70710678118654752f));
}
__device__ __forceinline__ uint32_t smem_u32(const void* p) {
    uint32_t a;
    asm("{ .reg .u64 t; cvta.to.shared.u64 t, %1; cvt.u32.u64 %0, t; }"
        : "=r"(a) : "l"(p));
    return a;
}
__device__ __forceinline__ void cp16(uint32_t dst, const void* src) {
    asm volatile("cp.async.cg.shared.global [%0], [%1], 16;" :: "r"(dst), "l"(src));
}
__device__ __forceinline__ void cp_commit() {
    asm volatile("cp.async.commit_group;" ::: "memory");
}
#define LDMX4(r0, r1, r2, r3, addr)                                           \
    asm volatile("ldmatrix.sync.aligned.m8n8.x4.shared.b16 {%0,%1,%2,%3}, [%4];" \
        : "=r"(r0), "=r"(r1), "=r"(r2), "=r"(r3) : "r"(addr))

// smem row: 32 k-halves data + 8 pad halves -> stride 40 halves (80B).
// Rows r within an 8-row ldmatrix tile hit banks (r*20)%32: all distinct.
#define OP_B     10240                     // bytes per operand tile (128*80)
#define STAGE_B  (2*OP_B)                  // 20480
#define STAGES   4
#define SMEM_DYN (STAGES*STAGE_B)          // 81920

// ---------------------------------------------------------------------------
// FP16 tensor-core GEMM: C[M,N] = A[M,K] @ Bt[N,K]^T  (A,Bt fp16)
//  EPI 0: store half             (C = __half*)
//  EPI 1: float store +res+bias  (C = float*, res fp32)
//  EPI 2: half store gelu(+bias)
//  EPI 3: fused attention gather (res = dots; scale rows by att, write to
//         permuted row n' = (m%32)*128 + m/32 of the same batch, half out)
// CTA 128x128, 128 threads (4 warps 2x2, warp tile 64x64), k-chunk 32,
// 4-stage cp.async pipeline, ldmatrix fragment loads.  (Mainloop = proven
// R5/R9 config, UNCHANGED.)
// ---------------------------------------------------------------------------
template <int EPI>
__global__ __launch_bounds__(128, 2) void gemm_fp16(
    const __half* __restrict__ A, const __half* __restrict__ Bt,
    void* __restrict__ Cv, const float* __restrict__ res,
    const float* __restrict__ bias, int M, int N, int K)
{
    extern __shared__ char smc[];
    const uint32_t smb = smem_u32(smc);

    const int tid  = threadIdx.x;
    const int lane = tid & 31;
    const int wid  = tid >> 5;
    const int wm   = wid >> 1;
    const int wn   = wid & 1;
    const int g    = lane >> 2;
    const int t    = lane & 3;
    const int m0   = blockIdx.y << 7;
    const int n0   = blockIdx.x << 7;

    const uint32_t aoff =
        (uint32_t)(((wm * 64 + (lane & 7) + 8 * ((lane >> 3) & 1)) * 40 +
                    8 * (lane >> 4)) * 2);
    const uint32_t boff =
        (uint32_t)(OP_B + (((wn * 64 + (lane & 7) + 8 * (lane >> 4)) * 40 +
                            8 * ((lane >> 3) & 1)) * 2));

    uint32_t sA[4], sB[4];
    const __half* gA[4];
    const __half* gB[4];
#pragma unroll
    for (int j = 0; j < 4; j++) {
        const int gid = j * 128 + tid;
        const int row = gid >> 2, c = gid & 3;
        sA[j] = (uint32_t)(row * 80 + c * 16);
        sB[j] = (uint32_t)(OP_B + row * 80 + c * 16);
        gA[j] = A  + (size_t)(m0 + row) * K + c * 8;
        gB[j] = Bt + (size_t)(n0 + row) * K + c * 8;
    }

    float acc[4][8][4];
#pragma unroll
    for (int i = 0; i < 4; i++)
#pragma unroll
        for (int j = 0; j < 8; j++)
#pragma unroll
            for (int r = 0; r < 4; r++) acc[i][j][r] = 0.f;

    const int KT = K >> 5;

#pragma unroll
    for (int s = 0; s < STAGES; s++) {
        const uint32_t base = smb + s * STAGE_B;
        const int ko = s * 32;
#pragma unroll
        for (int j = 0; j < 4; j++) {
            cp16(base + sA[j], gA[j] + ko);
            cp16(base + sB[j], gB[j] + ko);
        }
        cp_commit();
    }

    for (int kt = 0; kt < KT; kt++) {
        asm volatile("cp.async.wait_group %0;" :: "n"(STAGES - 1) : "memory");
        __syncthreads();

        const uint32_t stg = smb + (kt % STAGES) * STAGE_B;

#pragma unroll
        for (int kc = 0; kc < 2; kc++) {
            const uint32_t kb = kc * 32;
            uint32_t af[4][4];
#pragma unroll
            for (int i = 0; i < 4; i++)
                LDMX4(af[i][0], af[i][1], af[i][2], af[i][3],
                      stg + aoff + i * 1280 + kb);
            uint32_t bf[8][2];
#pragma unroll
            for (int jj = 0; jj < 4; jj++)
                LDMX4(bf[2 * jj][0], bf[2 * jj][1],
                      bf[2 * jj + 1][0], bf[2 * jj + 1][1],
                      stg + boff + jj * 1280 + kb);
#pragma unroll
            for (int i = 0; i < 4; i++)
#pragma unroll
                for (int j = 0; j < 8; j++) {
                    asm volatile(
                        "mma.sync.aligned.m16n8k16.row.col.f32.f16.f16.f32 "
                        "{%0,%1,%2,%3}, {%4,%5,%6,%7}, {%8,%9}, {%0,%1,%2,%3};"
                        : "+f"(acc[i][j][0]), "+f"(acc[i][j][1]),
                          "+f"(acc[i][j][2]), "+f"(acc[i][j][3])
                        : "r"(af[i][0]), "r"(af[i][1]),
                          "r"(af[i][2]), "r"(af[i][3]),
                          "r"(bf[j][0]), "r"(bf[j][1]));
                }
        }
        __syncthreads();

        const int nk = kt + STAGES;
        if (nk < KT) {
            const uint32_t base = smb + (nk % STAGES) * STAGE_B;
            const int ko = nk * 32;
#pragma unroll
            for (int j = 0; j < 4; j++) {
                cp16(base + sA[j], gA[j] + ko);
                cp16(base + sB[j], gB[j] + ko);
            }
        }
        cp_commit();
    }

    if (EPI == 3) {
        // fused gather epilogue: scale rows by att, stage half tile in smem,
        // store permuted rows contiguously.
        asm volatile("cp.async.wait_group 0;" ::: "memory");
        __syncthreads();
        const float* att = res;
        const int head = (n0 >> 6) + wn;           // constant per thread
        __half* st = (__half*)smc;                 // [128][136] halves
#pragma unroll
        for (int i = 0; i < 4; i++)
#pragma unroll
            for (int h = 0; h < 2; h++) {
                const int rl = wm * 64 + i * 16 + g + 8 * h;
                const int m = m0 + rl;
                const float a =
                    att[((size_t)((m >> 12) * HEADS + head)) * SEQ + (m & 4095)];
#pragma unroll
                for (int j = 0; j < 8; j++) {
                    const int col = wn * 64 + j * 8 + t * 2;
                    st[rl * 136 + col] =
                        __float2half(a * acc[i][j][2 * h + 0]);
                    st[rl * 136 + col + 1] =
                        __float2half(a * acc[i][j][2 * h + 1]);
                }
            }
        __syncthreads();
        const int cchunk = (tid & 15) * 8;         // 16 chunks of 8 cols
#pragma unroll
        for (int p = 0; p < 16; p++) {
            const int rl = p * 8 + (tid >> 4);
            const int m = m0 + rl;
            const int b = m >> 12, ml = m & 4095;
            const int np = (ml & 31) * 128 + (ml >> 5);   // inverse permutation
            const uint4 ou = *(const uint4*)(st + rl * 136 + cchunk);
            *(uint4*)((__half*)Cv + ((size_t)(b << 12) + np) * N + n0 + cchunk) = ou;
        }
        return;
    }

    // epilogue (EPI 0/1/2)
#pragma unroll
    for (int j = 0; j < 8; j++) {
        const int col = n0 + wn * 64 + j * 8 + t * 2;
        float2 bv = make_float2(0.f, 0.f);
        if (EPI == 1 || EPI == 2) bv = *(const float2*)&bias[col];
#pragma unroll
        for (int i = 0; i < 4; i++) {
            const int row0 = m0 + wm * 64 + i * 16 + g;
#pragma unroll
            for (int h = 0; h < 2; h++) {
                const int r = row0 + 8 * h;
                const float a = acc[i][j][2 * h + 0];
                const float b = acc[i][j][2 * h + 1];
                if (EPI == 0) {
                    *(__half2*)((__half*)Cv + (size_t)r * N + col) =
                        __floats2half2_rn(a, b);
                } else if (EPI == 1) {
                    const float2 rv = *(const float2*)&res[(size_t)r * N + col];
                    float2 o;
                    o.x = a + rv.x + bv.x;
                    o.y = b + rv.y + bv.y;
                    *(float2*)((float*)Cv + (size_t)r * N + col) = o;
                } else {
                    *(__half2*)((__half*)Cv + (size_t)r * N + col) =
                        __floats2half2_rn(gelu_exact(a + bv.x),
                                          gelu_exact(b + bv.y));
                }
            }
        }
    }
}

// ---------------------------------------------------------------------------
// QK GEMM with fused diagonal dot (R13-proven): CTA = (head, m-tile).
// B rows 0-63 = Q weights of head, 64-127 = K weights. Epilogue reduces the
// per-row 64-channel Q·K dot and writes dots directly; Q/K never hit gmem.
// ---------------------------------------------------------------------------
__global__ __launch_bounds__(128, 2) void gemm_qk_dots(
    const __half* __restrict__ A, const __half* __restrict__ BtAll,
    float* __restrict__ dots, int K)
{
    extern __shared__ char smc[];
    const uint32_t smb = smem_u32(smc);

    const int tid  = threadIdx.x;
    const int lane = tid & 31;
    const int wid  = tid >> 5;
    const int wm   = wid >> 1;
    const int wn   = wid & 1;
    const int g    = lane >> 2;
    const int t    = lane & 3;
    const int head = blockIdx.x;
    const int m0   = blockIdx.y << 7;

    const uint32_t aoff =
        (uint32_t)(((wm * 64 + (lane & 7) + 8 * ((lane >> 3) & 1)) * 40 +
                    8 * (lane >> 4)) * 2);
    const uint32_t boff =
        (uint32_t)(OP_B + (((wn * 64 + (lane & 7) + 8 * (lane >> 4)) * 40 +
                            8 * ((lane >> 3) & 1)) * 2));

    uint32_t sA[4], sB[4];
    const __half* gA[4];
    const __half* gB[4];
#pragma unroll
    for (int j = 0; j < 4; j++) {
        const int gid = j * 128 + tid;
        const int row = gid >> 2, c = gid & 3;
        sA[j] = (uint32_t)(row * 80 + c * 16);
        sB[j] = (uint32_t)(OP_B + row * 80 + c * 16);
        gA[j] = A + (size_t)(m0 + row) * K + c * 8;
        const int wrow = (row < 64) ? (head * 64 + row)
                                    : (1024 + head * 64 + (row - 64));
        gB[j] = BtAll + (size_t)wrow * K + c * 8;
    }

    float acc[4][8][4];
#pragma unroll
    for (int i = 0; i < 4; i++)
#pragma unroll
        for (int j = 0; j < 8; j++)
#pragma unroll
            for (int r = 0; r < 4; r++) acc[i][j][r] = 0.f;

    const int KT = K >> 5;

#pragma unroll
    for (int s = 0; s < STAGES; s++) {
        const uint32_t base = smb + s * STAGE_B;
        const int ko = s * 32;
#pragma unroll
        for (int j = 0; j < 4; j++) {
            cp16(base + sA[j], gA[j] + ko);
            cp16(base + sB[j], gB[j] + ko);
        }
        cp_commit();
    }

    for (int kt = 0; kt < KT; kt++) {
        asm volatile("cp.async.wait_group %0;" :: "n"(STAGES - 1) : "memory");
        __syncthreads();

        const uint32_t stg = smb + (kt % STAGES) * STAGE_B;

#pragma unroll
        for (int kc = 0; kc < 2; kc++) {
            const uint32_t kb = kc * 32;
            uint32_t af[4][4];
#pragma unroll
            for (int i = 0; i < 4; i++)
                LDMX4(af[i][0], af[i][1], af[i][2], af[i][3],
                      stg + aoff + i * 1280 + kb);
            uint32_t bf[8][2];
#pragma unroll
            for (int jj = 0; jj < 4; jj++)
                LDMX4(bf[2 * jj][0], bf[2 * jj][1],
                      bf[2 * jj + 1][0], bf[2 * jj + 1][1],
                      stg + boff + jj * 1280 + kb);
#pragma unroll
            for (int i = 0; i < 4; i++)
#pragma unroll
                for (int j = 0; j < 8; j++) {
                    asm volatile(
                        "mma.sync.aligned.m16n8k16.row.col.f32.f16.f16.f32 "
                        "{%0,%1,%2,%3}, {%4,%5,%6,%7}, {%8,%9}, {%0,%1,%2,%3};"
                        : "+f"(acc[i][j][0]), "+f"(acc[i][j][1]),
                          "+f"(acc[i][j][2]), "+f"(acc[i][j][3])
                        : "r"(af[i][0]), "r"(af[i][1]),
                          "r"(af[i][2]), "r"(af[i][3]),
                          "r"(bf[j][0]), "r"(bf[j][1]));
                }
        }
        __syncthreads();

        const int nk = kt + STAGES;
        if (nk < KT) {
            const uint32_t base = smb + (nk % STAGES) * STAGE_B;
            const int ko = nk * 32;
#pragma unroll
            for (int j = 0; j < 4; j++) {
                cp16(base + sA[j], gA[j] + ko);
                cp16(base + sB[j], gB[j] + ko);
            }
        }
        cp_commit();
    }

    // fused-dot epilogue: drain pipeline, reuse stage smem as fp32 Q/K tiles
    asm volatile("cp.async.wait_group 0;" ::: "memory");
    __syncthreads();

    float* smQ = (float*)smc;            // [128][65]
    float* smK = smQ + 128 * 65;         // [128][65]  (total 66560 B < 81920)
    float* dst = (wn == 0) ? smQ : smK;
#pragma unroll
    for (int j = 0; j < 8; j++) {
        const int col = j * 8 + t * 2;   // 0..62
#pragma unroll
        for (int i = 0; i < 4; i++) {
            const int row0 = wm * 64 + i * 16 + g;
#pragma unroll
            for (int h = 0; h < 2; h++) {
                const int r = row0 + 8 * h;
                dst[r * 65 + col]     = acc[i][j][2 * h + 0];
                dst[r * 65 + col + 1] = acc[i][j][2 * h + 1];
            }
        }
    }
    __syncthreads();

    {
        const float* qr = smQ + tid * 65;
        const float* kr = smK + tid * 65;
        float s = 0.f;
#pragma unroll
        for (int c = 0; c < 64; c++) s += qr[c] * kr[c];
        const int m = m0 + tid;
        dots[((size_t)((m >> 12) * HEADS + head)) * SEQ + (m & 4095)] =
            s * 0.125f;
    }
}

// ---------------------------------------------------------------------------
// All 6 weight transposes in ONE launch.
// ---------------------------------------------------------------------------
__global__ __launch_bounds__(256) void transpose_all(
    const float* __restrict__ wq, const float* __restrict__ wk,
    const float* __restrict__ wv, const float* __restrict__ wo,
    const float* __restrict__ w1, const float* __restrict__ w2,
    __half* __restrict__ wqkvT, __half* __restrict__ woT,
    __half* __restrict__ w1T, __half* __restrict__ w2T)
{
    __shared__ float sh[32][33];
    const int tile = blockIdx.x;
    const float* in;
    __half* out;
    int R, C, cx, ry;
    if (tile < 4096) {
        const int job = tile >> 10, loc = tile & 1023;
        cx = loc & 31; ry = loc >> 5; R = 1024; C = 1024;
        if (job == 0)      { in = wq; out = wqkvT; }
        else if (job == 1) { in = wk; out = wqkvT + (size_t)1024 * 1024; }
        else if (job == 2) { in = wv; out = wqkvT + (size_t)2 * 1024 * 1024; }
        else               { in = wo; out = woT; }
    } else if (tile < 8192) {
        const int loc = tile - 4096;
        cx = loc & 127; ry = loc >> 7; R = 1024; C = 4096;
        in = w1; out = w1T;
    } else {
        const int loc = tile - 8192;
        cx = loc & 31; ry = loc >> 5; R = 4096; C = 1024;
        in = w2; out = w2T;
    }
    const int c0 = cx * 32, r0 = ry * 32;
    const int tx = threadIdx.x, ty = threadIdx.y;
#pragma unroll
    for (int j = 0; j < 4; j++)
        sh[ty + j * 8][tx] = in[(size_t)(r0 + ty + j * 8) * C + c0 + tx];
    __syncthreads();
#pragma unroll
    for (int j = 0; j < 4; j++)
        out[(size_t)(c0 + ty + j * 8) * R + r0 + tx] = __float2half(sh[tx][ty + j * 8]);
}

// ---------------------------------------------------------------------------
// LayerNorm -> fp16 output, fully vectorized:
// one float4 load of x, float4 gamma/beta, one 8B store of 4 halves.
// ---------------------------------------------------------------------------
__global__ __launch_bounds__(256) void ln_kernel(
    const float* __restrict__ x, const float* __restrict__ gam,
    const float* __restrict__ bet, __half* __restrict__ out)
{
    const int row = blockIdx.x;
    const float4 v = ((const float4*)(x + (size_t)row * DIM))[threadIdx.x];
    float s  = v.x + v.y + v.z + v.w;
    float ss = v.x * v.x + v.y * v.y + v.z * v.z + v.w * v.w;
#pragma unroll
    for (int o = 16; o; o >>= 1) {
        s  += __shfl_xor_sync(0xffffffffu, s, o);
        ss += __shfl_xor_sync(0xffffffffu, ss, o);
    }
    __shared__ float sh1[8], sh2[8];
    const int w = threadIdx.x >> 5, l = threadIdx.x & 31;
    if (l == 0) { sh1[w] = s; sh2[w] = ss; }
    __syncthreads();
    s = 0.f; ss = 0.f;
#pragma unroll
    for (int i = 0; i < 8; i++) { s += sh1[i]; ss += sh2[i]; }
    const float mu   = s * (1.0f / DIM);
    const float var  = ss * (1.0f / DIM) - mu * mu;
    const float rstd = rsqrtf(var + 1e-5f);
    const float4 gv = ((const float4*)gam)[threadIdx.x];
    const float4 bv = ((const float4*)bet)[threadIdx.x];
    const __half2 o0 = __floats2half2_rn((v.x - mu) * rstd * gv.x + bv.x,
                                         (v.y - mu) * rstd * gv.y + bv.y);
    const __half2 o1 = __floats2half2_rn((v.z - mu) * rstd * gv.z + bv.z,
                                         (v.w - mu) * rstd * gv.w + bv.w);
    uint2 ou;
    ou.x = *(const uint32_t*)&o0;
    ou.y = *(const uint32_t*)&o1;
    ((uint2*)(out + (size_t)row * DIM))[threadIdx.x] = ou;
}

__global__ __launch_bounds__(1024) void softmax_kernel(float* __restrict__ d)
{
    const int row = blockIdx.x;
    float4* p = (float4*)(d + (size_t)row * SEQ);
    float4 v = p[threadIdx.x];
    float m = fmaxf(fmaxf(v.x, v.y), fmaxf(v.z, v.w));
#pragma unroll
    for (int o = 16; o; o >>= 1) m = fmaxf(m, __shfl_xor_sync(0xffffffffu, m, o));
    __shared__ float sm[32];
    const int w = threadIdx.x >> 5, l = threadIdx.x & 31;
    if (l == 0) sm[w] = m;
    __syncthreads();
    m = sm[0];
#pragma unroll
    for (int i = 1; i < 32; i++) m = fmaxf(m, sm[i]);
    __syncthreads();
    float4 e;
    e.x = expf(v.x - m); e.y = expf(v.y - m);
    e.z = expf(v.z - m); e.w = expf(v.w - m);
    float s = e.x + e.y + e.z + e.w;
#pragma unroll
    for (int o = 16; o; o >>= 1) s += __shfl_xor_sync(0xffffffffu, s, o);
    if (l == 0) sm[w] = s;
    __syncthreads();
    s = 0.f;
#pragma unroll
    for (int i = 0; i < 32; i++) s += sm[i];
    const float inv = 1.0f / s;
    e.x *= inv; e.y *= inv; e.z *= inv; e.w *= inv;
    p[threadIdx.x] = e;
}

// ---------------------------------------------------------------------------
// Launch
// ---------------------------------------------------------------------------
extern "C" void kernel_launch(void* const* d_in, const int* in_sizes, int n_in,
                              void* d_out, int out_size)
{
    const float* x     = (const float*)d_in[0];
    const float* ln1_g = (const float*)d_in[1];
    const float* ln1_b = (const float*)d_in[2];
    const float* wq    = (const float*)d_in[3];
    const float* wk    = (const float*)d_in[4];
    const float* wv    = (const float*)d_in[5];
    const float* wo    = (const float*)d_in[6];
    const float* bo    = (const float*)d_in[7];
    const float* ln2_g = (const float*)d_in[8];
    const float* ln2_b = (const float*)d_in[9];
    const float* w1    = (const float*)d_in[10];
    const float* b1    = (const float*)d_in[11];
    const float* w2    = (const float*)d_in[12];
    const float* b2    = (const float*)d_in[13];
    float* out = (float*)d_out;

    __half *h1, *ao, *h2, *act, *wqkvT, *woT, *w1T, *w2T;
    float *x2, *dots;
    cudaGetSymbolAddress((void**)&h1,   g_h1);
    cudaGetSymbolAddress((void**)&ao,   g_ao);
    cudaGetSymbolAddress((void**)&x2,   g_x2);
    cudaGetSymbolAddress((void**)&h2,   g_h2);
    cudaGetSymbolAddress((void**)&dots, g_dot);
    cudaGetSymbolAddress((void**)&act,  g_act);
    cudaGetSymbolAddress((void**)&wqkvT,g_wqkvT);
    cudaGetSymbolAddress((void**)&woT,  g_woT);
    cudaGetSymbolAddress((void**)&w1T,  g_w1T);
    cudaGetSymbolAddress((void**)&w2T,  g_w2T);

    cudaFuncSetAttribute(gemm_fp16<0>, cudaFuncAttributeMaxDynamicSharedMemorySize, SMEM_DYN);
    cudaFuncSetAttribute(gemm_fp16<1>, cudaFuncAttributeMaxDynamicSharedMemorySize, SMEM_DYN);
    cudaFuncSetAttribute(gemm_fp16<2>, cudaFuncAttributeMaxDynamicSharedMemorySize, SMEM_DYN);
    cudaFuncSetAttribute(gemm_fp16<3>, cudaFuncAttributeMaxDynamicSharedMemorySize, SMEM_DYN);
    cudaFuncSetAttribute(gemm_qk_dots, cudaFuncAttributeMaxDynamicSharedMemorySize, SMEM_DYN);

    // all 6 weight transposes in one launch (fp16 K-major B operands)
    transpose_all<<<12288, dim3(32, 8)>>>(wq, wk, wv, wo, w1, w2,
                                          wqkvT, woT, w1T, w2T);

    // 1. h1 = LN1(x)  (fp16, vectorized)
    ln_kernel<<<ROWS, 256>>>(x, ln1_g, ln1_b, h1);
    // 2. fused QK GEMM + diagonal dot -> dots (Q,K never hit gmem)
    gemm_qk_dots<<<dim3(HEADS, ROWS/128), 128, SMEM_DYN>>>(h1, wqkvT, dots, DIM);
    // 3. softmax over sequence per (b,h)
    softmax_kernel<<<BATCH * HEADS, 1024>>>(dots);
    // 4. V GEMM with fused gather epilogue: ao[b,n',c] = att*V, V never hits gmem
    gemm_fp16<3><<<dim3(DIM/128, ROWS/128), 128, SMEM_DYN>>>(
        h1, wqkvT + (size_t)2048 * DIM, ao, dots, nullptr, ROWS, DIM, DIM);
    // 5. x2 = x + ao @ wo + bo  (fp32 out)
    gemm_fp16<1><<<dim3(DIM/128, ROWS/128), 128, SMEM_DYN>>>(
        ao, woT, x2, x, bo, ROWS, DIM, DIM);
    // 6. h2 = LN2(x2)  (fp16, vectorized)
    ln_kernel<<<ROWS, 256>>>(x2, ln2_g, ln2_b, h2);
    // 7. act = gelu(h2 @ w1 + b1)  (fp16 out)
    gemm_fp16<2><<<dim3(DFF/128, ROWS/128), 128, SMEM_DYN>>>(
        h2, w1T, act, nullptr, b1, ROWS, DFF, DIM);
    // 8. out = x2 + act @ w2 + b2  (fp32 out)
    gemm_fp16<1><<<dim3(DIM/128, ROWS/128), 128, SMEM_DYN>>>(
        act, w2T, out, x2, b2, ROWS, DIM, DFF);
}

// round 17
// speedup vs baseline: 1.5697x; 1.0019x over previous
#include <cuda_runtime.h>
#include <cuda_fp16.h>
#include <math.h>
#include <stdint.h>

// Problem dims (fixed)
#define BATCH 4
#define SEQ   4096
#define DIM   1024
#define HEADS 16
#define DFF   4096
#define ROWS  16384
#define QKVW  3072

// ---------------------------------------------------------------------------
// Scratch (device globals; no runtime allocation allowed)
// ---------------------------------------------------------------------------
__device__ __half g_h1  [ROWS*(size_t)DIM];
__device__ __half g_ao  [ROWS*(size_t)DIM];
__device__ float  g_x2  [ROWS*(size_t)DIM];
__device__ __half g_h2  [ROWS*(size_t)DIM];
__device__ float  g_dot [BATCH*HEADS*(size_t)SEQ];
__device__ __half g_act [ROWS*(size_t)DFF];
__device__ __half g_wqkvT[(size_t)QKVW*DIM];   // [3072][1024] K-major (N rows)
__device__ __half g_woT [(size_t)DIM*DIM];
__device__ __half g_w1T [(size_t)DFF*DIM];
__device__ __half g_w2T [(size_t)DIM*DFF];

// ---------------------------------------------------------------------------
// Helpers
// ---------------------------------------------------------------------------
__device__ __forceinline__ float gelu_exact(float x) {
    return 0.5f * x * (1.0f + erff(x * 0.70710678118654752f));
}
__device__ __forceinline__ uint32_t smem_u32(const void* p) {
    uint32_t a;
    asm("{ .reg .u64 t; cvta.to.shared.u64 t, %1; cvt.u32.u64 %0, t; }"
        : "=r"(a) : "l"(p));
    return a;
}
__device__ __forceinline__ void cp16(uint32_t dst, const void* src) {
    asm volatile("cp.async.cg.shared.global [%0], [%1], 16;" :: "r"(dst), "l"(src));
}
__device__ __forceinline__ void cp_commit() {
    asm volatile("cp.async.commit_group;" ::: "memory");
}
#define LDMX4(r0, r1, r2, r3, addr)                                           \
    asm volatile("ldmatrix.sync.aligned.m8n8.x4.shared.b16 {%0,%1,%2,%3}, [%4];" \
        : "=r"(r0), "=r"(r1), "=r"(r2), "=r"(r3) : "r"(addr))

// smem row: 32 k-halves data + 8 pad halves -> stride 40 halves (80B).
// Rows r within an 8-row ldmatrix tile hit banks (r*20)%32: all distinct.
#define OP_B     10240                     // bytes per operand tile (128*80)
#define STAGE_B  (2*OP_B)                  // 20480
#define STAGES   4
#define SMEM_DYN (STAGES*STAGE_B)          // 81920

// ---------------------------------------------------------------------------
// FP16 tensor-core GEMM: C[M,N] = A[M,K] @ Bt[N,K]^T  (A,Bt fp16)
//  EPI 0: store half             (C = __half*)
//  EPI 1: float store +res+bias  (C = float*, res fp32)
//  EPI 2: half store gelu(+bias)
//  EPI 3: fused attention gather (res = dots; scale rows by att, write to
//         permuted row n' = (m%32)*128 + m/32 of the same batch, half out)
// CTA 128x128, 128 threads (4 warps 2x2, warp tile 64x64), k-chunk 32,
// 4-stage cp.async pipeline, ldmatrix fragment loads.  (Mainloop = proven
// R5/R9 config, UNCHANGED.)
// ---------------------------------------------------------------------------
template <int EPI>
__global__ __launch_bounds__(128, 2) void gemm_fp16(
    const __half* __restrict__ A, const __half* __restrict__ Bt,
    void* __restrict__ Cv, const float* __restrict__ res,
    const float* __restrict__ bias, int M, int N, int K)
{
    extern __shared__ char smc[];
    const uint32_t smb = smem_u32(smc);

    const int tid  = threadIdx.x;
    const int lane = tid & 31;
    const int wid  = tid >> 5;
    const int wm   = wid >> 1;
    const int wn   = wid & 1;
    const int g    = lane >> 2;
    const int t    = lane & 3;
    const int m0   = blockIdx.y << 7;
    const int n0   = blockIdx.x << 7;

    const uint32_t aoff =
        (uint32_t)(((wm * 64 + (lane & 7) + 8 * ((lane >> 3) & 1)) * 40 +
                    8 * (lane >> 4)) * 2);
    const uint32_t boff =
        (uint32_t)(OP_B + (((wn * 64 + (lane & 7) + 8 * (lane >> 4)) * 40 +
                            8 * ((lane >> 3) & 1)) * 2));

    uint32_t sA[4], sB[4];
    const __half* gA[4];
    const __half* gB[4];
#pragma unroll
    for (int j = 0; j < 4; j++) {
        const int gid = j * 128 + tid;
        const int row = gid >> 2, c = gid & 3;
        sA[j] = (uint32_t)(row * 80 + c * 16);
        sB[j] = (uint32_t)(OP_B + row * 80 + c * 16);
        gA[j] = A  + (size_t)(m0 + row) * K + c * 8;
        gB[j] = Bt + (size_t)(n0 + row) * K + c * 8;
    }

    float acc[4][8][4];
#pragma unroll
    for (int i = 0; i < 4; i++)
#pragma unroll
        for (int j = 0; j < 8; j++)
#pragma unroll
            for (int r = 0; r < 4; r++) acc[i][j][r] = 0.f;

    const int KT = K >> 5;

#pragma unroll
    for (int s = 0; s < STAGES; s++) {
        const uint32_t base = smb + s * STAGE_B;
        const int ko = s * 32;
#pragma unroll
        for (int j = 0; j < 4; j++) {
            cp16(base + sA[j], gA[j] + ko);
            cp16(base + sB[j], gB[j] + ko);
        }
        cp_commit();
    }

    for (int kt = 0; kt < KT; kt++) {
        asm volatile("cp.async.wait_group %0;" :: "n"(STAGES - 1) : "memory");
        __syncthreads();

        const uint32_t stg = smb + (kt % STAGES) * STAGE_B;

#pragma unroll
        for (int kc = 0; kc < 2; kc++) {
            const uint32_t kb = kc * 32;
            uint32_t af[4][4];
#pragma unroll
            for (int i = 0; i < 4; i++)
                LDMX4(af[i][0], af[i][1], af[i][2], af[i][3],
                      stg + aoff + i * 1280 + kb);
            uint32_t bf[8][2];
#pragma unroll
            for (int jj = 0; jj < 4; jj++)
                LDMX4(bf[2 * jj][0], bf[2 * jj][1],
                      bf[2 * jj + 1][0], bf[2 * jj + 1][1],
                      stg + boff + jj * 1280 + kb);
#pragma unroll
            for (int i = 0; i < 4; i++)
#pragma unroll
                for (int j = 0; j < 8; j++) {
                    asm volatile(
                        "mma.sync.aligned.m16n8k16.row.col.f32.f16.f16.f32 "
                        "{%0,%1,%2,%3}, {%4,%5,%6,%7}, {%8,%9}, {%0,%1,%2,%3};"
                        : "+f"(acc[i][j][0]), "+f"(acc[i][j][1]),
                          "+f"(acc[i][j][2]), "+f"(acc[i][j][3])
                        : "r"(af[i][0]), "r"(af[i][1]),
                          "r"(af[i][2]), "r"(af[i][3]),
                          "r"(bf[j][0]), "r"(bf[j][1]));
                }
        }
        __syncthreads();

        const int nk = kt + STAGES;
        if (nk < KT) {
            const uint32_t base = smb + (nk % STAGES) * STAGE_B;
            const int ko = nk * 32;
#pragma unroll
            for (int j = 0; j < 4; j++) {
                cp16(base + sA[j], gA[j] + ko);
                cp16(base + sB[j], gB[j] + ko);
            }
        }
        cp_commit();
    }

    if (EPI == 3) {
        // fused gather epilogue: scale rows by att, stage half tile in smem,
        // store permuted rows contiguously.
        asm volatile("cp.async.wait_group 0;" ::: "memory");
        __syncthreads();
        const float* att = res;
        const int head = (n0 >> 6) + wn;           // constant per thread
        __half* st = (__half*)smc;                 // [128][136] halves
#pragma unroll
        for (int i = 0; i < 4; i++)
#pragma unroll
            for (int h = 0; h < 2; h++) {
                const int rl = wm * 64 + i * 16 + g + 8 * h;
                const int m = m0 + rl;
                const float a =
                    att[((size_t)((m >> 12) * HEADS + head)) * SEQ + (m & 4095)];
#pragma unroll
                for (int j = 0; j < 8; j++) {
                    const int col = wn * 64 + j * 8 + t * 2;
                    st[rl * 136 + col] =
                        __float2half(a * acc[i][j][2 * h + 0]);
                    st[rl * 136 + col + 1] =
                        __float2half(a * acc[i][j][2 * h + 1]);
                }
            }
        __syncthreads();
        const int cchunk = (tid & 15) * 8;         // 16 chunks of 8 cols
#pragma unroll
        for (int p = 0; p < 16; p++) {
            const int rl = p * 8 + (tid >> 4);
            const int m = m0 + rl;
            const int b = m >> 12, ml = m & 4095;
            const int np = (ml & 31) * 128 + (ml >> 5);   // inverse permutation
            const uint4 ou = *(const uint4*)(st + rl * 136 + cchunk);
            *(uint4*)((__half*)Cv + ((size_t)(b << 12) + np) * N + n0 + cchunk) = ou;
        }
        return;
    }

    // epilogue (EPI 0/1/2)
#pragma unroll
    for (int j = 0; j < 8; j++) {
        const int col = n0 + wn * 64 + j * 8 + t * 2;
        float2 bv = make_float2(0.f, 0.f);
        if (EPI == 1 || EPI == 2) bv = *(const float2*)&bias[col];
#pragma unroll
        for (int i = 0; i < 4; i++) {
            const int row0 = m0 + wm * 64 + i * 16 + g;
#pragma unroll
            for (int h = 0; h < 2; h++) {
                const int r = row0 + 8 * h;
                const float a = acc[i][j][2 * h + 0];
                const float b = acc[i][j][2 * h + 1];
                if (EPI == 0) {
                    *(__half2*)((__half*)Cv + (size_t)r * N + col) =
                        __floats2half2_rn(a, b);
                } else if (EPI == 1) {
                    const float2 rv = *(const float2*)&res[(size_t)r * N + col];
                    float2 o;
                    o.x = a + rv.x + bv.x;
                    o.y = b + rv.y + bv.y;
                    *(float2*)((float*)Cv + (size_t)r * N + col) = o;
                } else {
                    *(__half2*)((__half*)Cv + (size_t)r * N + col) =
                        __floats2half2_rn(gelu_exact(a + bv.x),
                                          gelu_exact(b + bv.y));
                }
            }
        }
    }
}

// ---------------------------------------------------------------------------
// QK GEMM with fused diagonal dot (R13-proven): CTA = (head, m-tile).
// B rows 0-63 = Q weights of head, 64-127 = K weights. Epilogue reduces the
// per-row 64-channel Q·K dot and writes dots directly; Q/K never hit gmem.
// ---------------------------------------------------------------------------
__global__ __launch_bounds__(128, 2) void gemm_qk_dots(
    const __half* __restrict__ A, const __half* __restrict__ BtAll,
    float* __restrict__ dots, int K)
{
    extern __shared__ char smc[];
    const uint32_t smb = smem_u32(smc);

    const int tid  = threadIdx.x;
    const int lane = tid & 31;
    const int wid  = tid >> 5;
    const int wm   = wid >> 1;
    const int wn   = wid & 1;
    const int g    = lane >> 2;
    const int t    = lane & 3;
    const int head = blockIdx.x;
    const int m0   = blockIdx.y << 7;

    const uint32_t aoff =
        (uint32_t)(((wm * 64 + (lane & 7) + 8 * ((lane >> 3) & 1)) * 40 +
                    8 * (lane >> 4)) * 2);
    const uint32_t boff =
        (uint32_t)(OP_B + (((wn * 64 + (lane & 7) + 8 * (lane >> 4)) * 40 +
                            8 * ((lane >> 3) & 1)) * 2));

    uint32_t sA[4], sB[4];
    const __half* gA[4];
    const __half* gB[4];
#pragma unroll
    for (int j = 0; j < 4; j++) {
        const int gid = j * 128 + tid;
        const int row = gid >> 2, c = gid & 3;
        sA[j] = (uint32_t)(row * 80 + c * 16);
        sB[j] = (uint32_t)(OP_B + row * 80 + c * 16);
        gA[j] = A + (size_t)(m0 + row) * K + c * 8;
        const int wrow = (row < 64) ? (head * 64 + row)
                                    : (1024 + head * 64 + (row - 64));
        gB[j] = BtAll + (size_t)wrow * K + c * 8;
    }

    float acc[4][8][4];
#pragma unroll
    for (int i = 0; i < 4; i++)
#pragma unroll
        for (int j = 0; j < 8; j++)
#pragma unroll
            for (int r = 0; r < 4; r++) acc[i][j][r] = 0.f;

    const int KT = K >> 5;

#pragma unroll
    for (int s = 0; s < STAGES; s++) {
        const uint32_t base = smb + s * STAGE_B;
        const int ko = s * 32;
#pragma unroll
        for (int j = 0; j < 4; j++) {
            cp16(base + sA[j], gA[j] + ko);
            cp16(base + sB[j], gB[j] + ko);
        }
        cp_commit();
    }

    for (int kt = 0; kt < KT; kt++) {
        asm volatile("cp.async.wait_group %0;" :: "n"(STAGES - 1) : "memory");
        __syncthreads();

        const uint32_t stg = smb + (kt % STAGES) * STAGE_B;

#pragma unroll
        for (int kc = 0; kc < 2; kc++) {
            const uint32_t kb = kc * 32;
            uint32_t af[4][4];
#pragma unroll
            for (int i = 0; i < 4; i++)
                LDMX4(af[i][0], af[i][1], af[i][2], af[i][3],
                      stg + aoff + i * 1280 + kb);
            uint32_t bf[8][2];
#pragma unroll
            for (int jj = 0; jj < 4; jj++)
                LDMX4(bf[2 * jj][0], bf[2 * jj][1],
                      bf[2 * jj + 1][0], bf[2 * jj + 1][1],
                      stg + boff + jj * 1280 + kb);
#pragma unroll
            for (int i = 0; i < 4; i++)
#pragma unroll
                for (int j = 0; j < 8; j++) {
                    asm volatile(
                        "mma.sync.aligned.m16n8k16.row.col.f32.f16.f16.f32 "
                        "{%0,%1,%2,%3}, {%4,%5,%6,%7}, {%8,%9}, {%0,%1,%2,%3};"
                        : "+f"(acc[i][j][0]), "+f"(acc[i][j][1]),
                          "+f"(acc[i][j][2]), "+f"(acc[i][j][3])
                        : "r"(af[i][0]), "r"(af[i][1]),
                          "r"(af[i][2]), "r"(af[i][3]),
                          "r"(bf[j][0]), "r"(bf[j][1]));
                }
        }
        __syncthreads();

        const int nk = kt + STAGES;
        if (nk < KT) {
            const uint32_t base = smb + (nk % STAGES) * STAGE_B;
            const int ko = nk * 32;
#pragma unroll
            for (int j = 0; j < 4; j++) {
                cp16(base + sA[j], gA[j] + ko);
                cp16(base + sB[j], gB[j] + ko);
            }
        }
        cp_commit();
    }

    // fused-dot epilogue: drain pipeline, reuse stage smem as fp32 Q/K tiles
    asm volatile("cp.async.wait_group 0;" ::: "memory");
    __syncthreads();

    float* smQ = (float*)smc;            // [128][65]
    float* smK = smQ + 128 * 65;         // [128][65]  (total 66560 B < 81920)
    float* dst = (wn == 0) ? smQ : smK;
#pragma unroll
    for (int j = 0; j < 8; j++) {
        const int col = j * 8 + t * 2;   // 0..62
#pragma unroll
        for (int i = 0; i < 4; i++) {
            const int row0 = wm * 64 + i * 16 + g;
#pragma unroll
            for (int h = 0; h < 2; h++) {
                const int r = row0 + 8 * h;
                dst[r * 65 + col]     = acc[i][j][2 * h + 0];
                dst[r * 65 + col + 1] = acc[i][j][2 * h + 1];
            }
        }
    }
    __syncthreads();

    {
        const float* qr = smQ + tid * 65;
        const float* kr = smK + tid * 65;
        float s = 0.f;
#pragma unroll
        for (int c = 0; c < 64; c++) s += qr[c] * kr[c];
        const int m = m0 + tid;
        dots[((size_t)((m >> 12) * HEADS + head)) * SEQ + (m & 4095)] =
            s * 0.125f;
    }
}

// ---------------------------------------------------------------------------
// All 6 weight transposes in ONE launch, vectorized store phase (R17):
// loads unchanged (coalesced floats into stride-33 smem); store phase remaps
// 256 threads so each writes one 8B uint2 of 4 halves (full store efficiency,
// conflict-free smem reads: bank (4k+ci) mod 32 distinct across the warp).
// ---------------------------------------------------------------------------
__global__ __launch_bounds__(256) void transpose_all(
    const float* __restrict__ wq, const float* __restrict__ wk,
    const float* __restrict__ wv, const float* __restrict__ wo,
    const float* __restrict__ w1, const float* __restrict__ w2,
    __half* __restrict__ wqkvT, __half* __restrict__ woT,
    __half* __restrict__ w1T, __half* __restrict__ w2T)
{
    __shared__ float sh[32][33];
    const int tile = blockIdx.x;
    const float* in;
    __half* out;
    int R, C, cx, ry;
    if (tile < 4096) {
        const int job = tile >> 10, loc = tile & 1023;
        cx = loc & 31; ry = loc >> 5; R = 1024; C = 1024;
        if (job == 0)      { in = wq; out = wqkvT; }
        else if (job == 1) { in = wk; out = wqkvT + (size_t)1024 * 1024; }
        else if (job == 2) { in = wv; out = wqkvT + (size_t)2 * 1024 * 1024; }
        else               { in = wo; out = woT; }
    } else if (tile < 8192) {
        const int loc = tile - 4096;
        cx = loc & 127; ry = loc >> 7; R = 1024; C = 4096;
        in = w1; out = w1T;
    } else {
        const int loc = tile - 8192;
        cx = loc & 31; ry = loc >> 5; R = 4096; C = 1024;
        in = w2; out = w2T;
    }
    const int c0 = cx * 32, r0 = ry * 32;
    const int tx = threadIdx.x & 31, ty = threadIdx.x >> 5;
#pragma unroll
    for (int j = 0; j < 4; j++)
        sh[ty + j * 8][tx] = in[(size_t)(r0 + ty + j * 8) * C + c0 + tx];
    __syncthreads();
    // store: thread -> output row ci = tid/8, element chunk rk = (tid%8)*4
    const int ci = threadIdx.x >> 3;
    const int rk = (threadIdx.x & 7) * 4;
    __half hv[4];
#pragma unroll
    for (int e = 0; e < 4; e++) hv[e] = __float2half(sh[rk + e][ci]);
    *(uint2*)&out[(size_t)(c0 + ci) * R + r0 + rk] = *(const uint2*)hv;
}

// ---------------------------------------------------------------------------
// LayerNorm -> fp16 output, fully vectorized:
// one float4 load of x, float4 gamma/beta, one 8B store of 4 halves.
// ---------------------------------------------------------------------------
__global__ __launch_bounds__(256) void ln_kernel(
    const float* __restrict__ x, const float* __restrict__ gam,
    const float* __restrict__ bet, __half* __restrict__ out)
{
    const int row = blockIdx.x;
    const float4 v = ((const float4*)(x + (size_t)row * DIM))[threadIdx.x];
    float s  = v.x + v.y + v.z + v.w;
    float ss = v.x * v.x + v.y * v.y + v.z * v.z + v.w * v.w;
#pragma unroll
    for (int o = 16; o; o >>= 1) {
        s  += __shfl_xor_sync(0xffffffffu, s, o);
        ss += __shfl_xor_sync(0xffffffffu, ss, o);
    }
    __shared__ float sh1[8], sh2[8];
    const int w = threadIdx.x >> 5, l = threadIdx.x & 31;
    if (l == 0) { sh1[w] = s; sh2[w] = ss; }
    __syncthreads();
    s = 0.f; ss = 0.f;
#pragma unroll
    for (int i = 0; i < 8; i++) { s += sh1[i]; ss += sh2[i]; }
    const float mu   = s * (1.0f / DIM);
    const float var  = ss * (1.0f / DIM) - mu * mu;
    const float rstd = rsqrtf(var + 1e-5f);
    const float4 gv = ((const float4*)gam)[threadIdx.x];
    const float4 bv = ((const float4*)bet)[threadIdx.x];
    const __half2 o0 = __floats2half2_rn((v.x - mu) * rstd * gv.x + bv.x,
                                         (v.y - mu) * rstd * gv.y + bv.y);
    const __half2 o1 = __floats2half2_rn((v.z - mu) * rstd * gv.z + bv.z,
                                         (v.w - mu) * rstd * gv.w + bv.w);
    uint2 ou;
    ou.x = *(const uint32_t*)&o0;
    ou.y = *(const uint32_t*)&o1;
    ((uint2*)(out + (size_t)row * DIM))[threadIdx.x] = ou;
}

__global__ __launch_bounds__(1024) void softmax_kernel(float* __restrict__ d)
{
    const int row = blockIdx.x;
    float4* p = (float4*)(d + (size_t)row * SEQ);
    float4 v = p[threadIdx.x];
    float m = fmaxf(fmaxf(v.x, v.y), fmaxf(v.z, v.w));
#pragma unroll
    for (int o = 16; o; o >>= 1) m = fmaxf(m, __shfl_xor_sync(0xffffffffu, m, o));
    __shared__ float sm[32];
    const int w = threadIdx.x >> 5, l = threadIdx.x & 31;
    if (l == 0) sm[w] = m;
    __syncthreads();
    m = sm[0];
#pragma unroll
    for (int i = 1; i < 32; i++) m = fmaxf(m, sm[i]);
    __syncthreads();
    float4 e;
    e.x = expf(v.x - m); e.y = expf(v.y - m);
    e.z = expf(v.z - m); e.w = expf(v.w - m);
    float s = e.x + e.y + e.z + e.w;
#pragma unroll
    for (int o = 16; o; o >>= 1) s += __shfl_xor_sync(0xffffffffu, s, o);
    if (l == 0) sm[w] = s;
    __syncthreads();
    s = 0.f;
#pragma unroll
    for (int i = 0; i < 32; i++) s += sm[i];
    const float inv = 1.0f / s;
    e.x *= inv; e.y *= inv; e.z *= inv; e.w *= inv;
    p[threadIdx.x] = e;
}

// ---------------------------------------------------------------------------
// Launch
// ---------------------------------------------------------------------------
extern "C" void kernel_launch(void* const* d_in, const int* in_sizes, int n_in,
                              void* d_out, int out_size)
{
    const float* x     = (const float*)d_in[0];
    const float* ln1_g = (const float*)d_in[1];
    const float* ln1_b = (const float*)d_in[2];
    const float* wq    = (const float*)d_in[3];
    const float* wk    = (const float*)d_in[4];
    const float* wv    = (const float*)d_in[5];
    const float* wo    = (const float*)d_in[6];
    const float* bo    = (const float*)d_in[7];
    const float* ln2_g = (const float*)d_in[8];
    const float* ln2_b = (const float*)d_in[9];
    const float* w1    = (const float*)d_in[10];
    const float* b1    = (const float*)d_in[11];
    const float* w2    = (const float*)d_in[12];
    const float* b2    = (const float*)d_in[13];
    float* out = (float*)d_out;

    __half *h1, *ao, *h2, *act, *wqkvT, *woT, *w1T, *w2T;
    float *x2, *dots;
    cudaGetSymbolAddress((void**)&h1,   g_h1);
    cudaGetSymbolAddress((void**)&ao,   g_ao);
    cudaGetSymbolAddress((void**)&x2,   g_x2);
    cudaGetSymbolAddress((void**)&h2,   g_h2);
    cudaGetSymbolAddress((void**)&dots, g_dot);
    cudaGetSymbolAddress((void**)&act,  g_act);
    cudaGetSymbolAddress((void**)&wqkvT,g_wqkvT);
    cudaGetSymbolAddress((void**)&woT,  g_woT);
    cudaGetSymbolAddress((void**)&w1T,  g_w1T);
    cudaGetSymbolAddress((void**)&w2T,  g_w2T);

    cudaFuncSetAttribute(gemm_fp16<0>, cudaFuncAttributeMaxDynamicSharedMemorySize, SMEM_DYN);
    cudaFuncSetAttribute(gemm_fp16<1>, cudaFuncAttributeMaxDynamicSharedMemorySize, SMEM_DYN);
    cudaFuncSetAttribute(gemm_fp16<2>, cudaFuncAttributeMaxDynamicSharedMemorySize, SMEM_DYN);
    cudaFuncSetAttribute(gemm_fp16<3>, cudaFuncAttributeMaxDynamicSharedMemorySize, SMEM_DYN);
    cudaFuncSetAttribute(gemm_qk_dots, cudaFuncAttributeMaxDynamicSharedMemorySize, SMEM_DYN);

    // all 6 weight transposes in one launch (fp16 K-major B operands)
    transpose_all<<<12288, 256>>>(wq, wk, wv, wo, w1, w2,
                                  wqkvT, woT, w1T, w2T);

    // 1. h1 = LN1(x)  (fp16, vectorized)
    ln_kernel<<<ROWS, 256>>>(x, ln1_g, ln1_b, h1);
    // 2. fused QK GEMM + diagonal dot -> dots (Q,K never hit gmem)
    gemm_qk_dots<<<dim3(HEADS, ROWS/128), 128, SMEM_DYN>>>(h1, wqkvT, dots, DIM);
    // 3. softmax over sequence per (b,h)
    softmax_kernel<<<BATCH * HEADS, 1024>>>(dots);
    // 4. V GEMM with fused gather epilogue: ao[b,n',c] = att*V, V never hits gmem
    gemm_fp16<3><<<dim3(DIM/128, ROWS/128), 128, SMEM_DYN>>>(
        h1, wqkvT + (size_t)2048 * DIM, ao, dots, nullptr, ROWS, DIM, DIM);
    // 5. x2 = x + ao @ wo + bo  (fp32 out)
    gemm_fp16<1><<<dim3(DIM/128, ROWS/128), 128, SMEM_DYN>>>(
        ao, woT, x2, x, bo, ROWS, DIM, DIM);
    // 6. h2 = LN2(x2)  (fp16, vectorized)
    ln_kernel<<<ROWS, 256>>>(x2, ln2_g, ln2_b, h2);
    // 7. act = gelu(h2 @ w1 + b1)  (fp16 out)
    gemm_fp16<2><<<dim3(DFF/128, ROWS/128), 128, SMEM_DYN>>>(
        h2, w1T, act, nullptr, b1, ROWS, DFF, DIM);
    // 8. out = x2 + act @ w2 + b2  (fp32 out)
    gemm_fp16<1><<<dim3(DIM/128, ROWS/128), 128, SMEM_DYN>>>(
        act, w2T, out, x2, b2, ROWS, DIM, DFF);
}